// round 2
// baseline (speedup 1.0000x reference)
#include <cuda_runtime.h>
#include <cuda_bf16.h>
#include <math.h>

#define NB 4
#define NP 2048
#define NC 128
#define ND 384
#define NH 6
#define FD 192
#define M3 (3*NP)   // 6144

// ---------------- scratch (device globals; no allocation allowed) ----------------
__device__ float g_normx[NB*NC*3*NP];
__device__ float g_q [NB*ND*3*NP];
__device__ float g_k [NB*ND*3*NP];
__device__ float g_v [NB*ND*3*NP];
__device__ float g_ao[NB*ND*3*NP];
__device__ float g_G [NB*NP*1536];          // per point: [i(3)][a(4)][o(128)]
__device__ float g_x5[NB*2*NC*3*NP];        // concat [attn_proj ; knn_pool]
__device__ float g_vnx[NB*NC*3*NP];
__device__ float g_nx2[NB*NC*3*NP];
__device__ float g_p3[NB*2*NC*3*NP];
__device__ float g_d3[NB*2*NC*3*NP];
__device__ float g_h [NB*2*NC*3*NP];
__device__ float g_p4[NB*NC*3*NP];
__device__ float g_d4[NB*NC*3*NP];
__device__ float g_cw[512*128];

// ---------------- weight prep: CW = [W1a ; W1b-W1a ; U1a ; U1b-U1a] ----------------
__global__ void prep_cw(const float* __restrict__ W1, const float* __restrict__ U1,
                        float* __restrict__ CW)
{
    int idx = blockIdx.x * 256 + threadIdx.x;   // 512*128
    if (idx >= 512*128) return;
    int col = idx >> 7;      // 0..511 = a*128+o
    int c   = idx & 127;
    int a = col >> 7;        // wrong: col/128
    a = col / 128;
    int o = col % 128;
    float v;
    if      (a == 0) v = W1[o*256 + c];
    else if (a == 1) v = W1[o*256 + 128 + c] - W1[o*256 + c];
    else if (a == 2) v = U1[o*256 + c];
    else             v = U1[o*256 + 128 + c] - U1[o*256 + c];
    CW[col*128 + c] = v;
}

// ---------------- vector-norm layernorm ----------------
// mode 0: input x (B,N,384);  mode 1: input (B,128,3,N). Output (B,128,3,N).
__global__ __launch_bounds__(128) void ln_k(const float* __restrict__ in,
                                            const float* __restrict__ g,
                                            const float* __restrict__ bb,
                                            float* __restrict__ out, int mode)
{
    int bn = blockIdx.x;
    int b = bn >> 11, n = bn & 2047;
    int c = threadIdx.x;
    float v0, v1, v2;
    if (mode == 0) {
        const float* p = in + (long long)bn*384 + 3*c;
        v0 = p[0]; v1 = p[1]; v2 = p[2];
    } else {
        const float* p = in + ((long long)b*NC + c)*M3 + n;
        v0 = p[0]; v1 = p[2048]; v2 = p[4096];
    }
    float nrm = sqrtf(v0*v0 + v1*v1 + v2*v2 + 1e-6f);
    float s = nrm, s2 = nrm*nrm;
    for (int m = 16; m; m >>= 1) {
        s  += __shfl_xor_sync(0xffffffffu, s,  m);
        s2 += __shfl_xor_sync(0xffffffffu, s2, m);
    }
    __shared__ float sb[8];
    int w = c >> 5, lane = c & 31;
    if (!lane) { sb[w] = s; sb[4 + w] = s2; }
    __syncthreads();
    float ts  = sb[0] + sb[1] + sb[2] + sb[3];
    float ts2 = sb[4] + sb[5] + sb[6] + sb[7];
    float mu  = ts * (1.f/128.f);
    float var = ts2 * (1.f/128.f) - mu*mu;
    float nhat = (nrm - mu) / sqrtf(var + 1e-5f);
    float scale = (g[c]*nhat + bb[c]) / nrm;
    float* q = out + ((long long)b*NC + c)*M3 + n;
    q[0] = v0*scale; q[2048] = v1*scale; q[4096] = v2*scale;
}

// ---------------- generic batched GEMM: Y[o,m] = sum_c W[o,c] * X[c*ldx + m] ----------------
// BM=BN=128, BK=16, 256 thr, 8x8 micro. O,M multiples of 128; Cin multiple of 16.
// mode 1: add residual  Res[b*N*384 + (m%2048)*384 + 3*o + m/2048]  (x-layout)
__global__ __launch_bounds__(256) void gemm_k(
    const float* __restrict__ W, const float* __restrict__ X, float* __restrict__ Y,
    const float* __restrict__ Res,
    int Cin, int ldx,
    long long xsb, long long xsi, long long ysb, long long ysi,
    int oso, int osm, int zflag, int mode)
{
    __shared__ float sw[16*132];
    __shared__ float sx[16*128];
    int z = blockIdx.z;
    int b  = zflag ? z/3 : z;
    int i3 = zflag ? z%3 : 0;
    const float* xb = X + (long long)b*xsb + (long long)i3*xsi;
    float* yb = Y + (long long)b*ysb + (long long)i3*ysi;
    int m0 = blockIdx.x * 128;
    int o0 = blockIdx.y * 128;
    int tid = threadIdx.x;
    int to = tid >> 4, tm = tid & 15;
    float acc[8][8];
    #pragma unroll
    for (int i = 0; i < 8; i++)
        #pragma unroll
        for (int j = 0; j < 8; j++) acc[i][j] = 0.f;

    for (int k0 = 0; k0 < Cin; k0 += 16) {
        #pragma unroll
        for (int t = 0; t < 2; t++) {
            int l4 = tid + t*256;
            int row = l4 >> 2;
            int kc  = (l4 & 3) << 2;
            float4 w4 = *(const float4*)(W + (long long)(o0 + row)*Cin + k0 + kc);
            sw[(kc+0)*132 + row] = w4.x;
            sw[(kc+1)*132 + row] = w4.y;
            sw[(kc+2)*132 + row] = w4.z;
            sw[(kc+3)*132 + row] = w4.w;
        }
        #pragma unroll
        for (int t = 0; t < 2; t++) {
            int l4 = tid + t*256;
            int kr = l4 >> 5;
            int mc = (l4 & 31) << 2;
            *(float4*)(sx + kr*128 + mc) =
                *(const float4*)(xb + (long long)(k0 + kr)*ldx + m0 + mc);
        }
        __syncthreads();
        #pragma unroll
        for (int kk = 0; kk < 16; kk++) {
            float wf[8], xf[8];
            *(float4*)(wf)     = *(float4*)(sw + kk*132 + to*8);
            *(float4*)(wf + 4) = *(float4*)(sw + kk*132 + to*8 + 4);
            *(float4*)(xf)     = *(float4*)(sx + kk*128 + tm*8);
            *(float4*)(xf + 4) = *(float4*)(sx + kk*128 + tm*8 + 4);
            #pragma unroll
            for (int i = 0; i < 8; i++)
                #pragma unroll
                for (int j = 0; j < 8; j++)
                    acc[i][j] += wf[i]*xf[j];
        }
        __syncthreads();
    }

    int ob = o0 + to*8, mb = m0 + tm*8;
    if (mode == 1) {
        #pragma unroll
        for (int i = 0; i < 8; i++)
            #pragma unroll
            for (int j = 0; j < 8; j++) {
                int o = ob + i, m = mb + j;
                acc[i][j] += Res[(long long)b*NP*ND + (long long)(m & 2047)*ND + 3*o + (m >> 11)];
            }
    }
    if (osm == 1) {
        #pragma unroll
        for (int i = 0; i < 8; i++) {
            float4 v0 = make_float4(acc[i][0], acc[i][1], acc[i][2], acc[i][3]);
            float4 v1 = make_float4(acc[i][4], acc[i][5], acc[i][6], acc[i][7]);
            float* p = yb + (long long)(ob + i)*oso + mb;
            *(float4*)(p)     = v0;
            *(float4*)(p + 4) = v1;
        }
    } else if (oso == 1) {
        #pragma unroll
        for (int j = 0; j < 8; j++) {
            float4 v0 = make_float4(acc[0][j], acc[1][j], acc[2][j], acc[3][j]);
            float4 v1 = make_float4(acc[4][j], acc[5][j], acc[6][j], acc[7][j]);
            float* p = yb + (long long)(mb + j)*osm + ob;
            *(float4*)(p)     = v0;
            *(float4*)(p + 4) = v1;
        }
    } else {
        #pragma unroll
        for (int i = 0; i < 8; i++)
            #pragma unroll
            for (int j = 0; j < 8; j++)
                yb[(long long)(ob + i)*oso + (long long)(mb + j)*osm] = acc[i][j];
    }
}

// ---------------- flash attention (fp32, online softmax) ----------------
// Q/K/V/O viewed as (B,H,192,N). Block: 64 queries, stream 64-key tiles.
#define FSMEM ((3*64*193 + 64*65) * 4)
__global__ __launch_bounds__(256) void flash_k(const float* __restrict__ Q,
                                               const float* __restrict__ K,
                                               const float* __restrict__ V,
                                               float* __restrict__ O)
{
    extern __shared__ float sm[];
    float* Qs = sm;                 // [64][193]
    float* Ks = sm + 64*193;
    float* Vs = sm + 2*64*193;
    float* Ps = sm + 3*64*193;      // [64][65]
    int n0 = blockIdx.x * 64;
    long long hb = (long long)(blockIdx.z*NH + blockIdx.y) * FD * NP;
    const float* Qb = Q + hb;
    const float* Kb = K + hb;
    const float* Vb = V + hb;
    float* Ob = O + hb;
    int tid = threadIdx.x;
    int tq = tid >> 4, tx = tid & 15;

    for (int l = tid; l < 64*FD; l += 256) {
        int r = l & 63, d = l >> 6;
        Qs[r*193 + d] = Qb[(long long)d*NP + n0 + r];
    }
    float m_run[4], l_run[4], acc[4][12];
    #pragma unroll
    for (int q = 0; q < 4; q++) {
        m_run[q] = -1e30f; l_run[q] = 0.f;
        #pragma unroll
        for (int j = 0; j < 12; j++) acc[q][j] = 0.f;
    }
    __syncthreads();

    for (int kt = 0; kt < NP; kt += 64) {
        for (int l = tid; l < 64*FD; l += 256) {
            int r = l & 63, d = l >> 6;
            Ks[r*193 + d] = Kb[(long long)d*NP + kt + r];
            Vs[r*193 + d] = Vb[(long long)d*NP + kt + r];
        }
        __syncthreads();

        float s[4][4];
        #pragma unroll
        for (int q = 0; q < 4; q++)
            #pragma unroll
            for (int j = 0; j < 4; j++) s[q][j] = 0.f;
        #pragma unroll 2
        for (int dd = 0; dd < FD; dd++) {
            float qv[4], kv[4];
            #pragma unroll
            for (int q = 0; q < 4; q++) qv[q] = Qs[(tq*4 + q)*193 + dd];
            #pragma unroll
            for (int j = 0; j < 4; j++) kv[j] = Ks[(tx*4 + j)*193 + dd];
            #pragma unroll
            for (int q = 0; q < 4; q++)
                #pragma unroll
                for (int j = 0; j < 4; j++)
                    s[q][j] += qv[q]*kv[j];
        }
        #pragma unroll
        for (int q = 0; q < 4; q++) {
            float mx = -1e30f;
            #pragma unroll
            for (int j = 0; j < 4; j++) { s[q][j] *= 0.125f; mx = fmaxf(mx, s[q][j]); }
            for (int sh = 8; sh; sh >>= 1)
                mx = fmaxf(mx, __shfl_xor_sync(0xffffffffu, mx, sh));
            float mn = fmaxf(m_run[q], mx);
            float alpha = __expf(m_run[q] - mn);
            m_run[q] = mn;
            float ps = 0.f;
            #pragma unroll
            for (int j = 0; j < 4; j++) {
                float p = __expf(s[q][j] - mn);
                Ps[(tq*4 + q)*65 + tx*4 + j] = p;
                ps += p;
            }
            for (int sh = 8; sh; sh >>= 1)
                ps += __shfl_xor_sync(0xffffffffu, ps, sh);
            l_run[q] = l_run[q]*alpha + ps;
            #pragma unroll
            for (int j = 0; j < 12; j++) acc[q][j] *= alpha;
        }
        __syncthreads();

        #pragma unroll 2
        for (int kk = 0; kk < 64; kk++) {
            float pv[4];
            #pragma unroll
            for (int q = 0; q < 4; q++) pv[q] = Ps[(tq*4 + q)*65 + kk];
            #pragma unroll
            for (int j = 0; j < 12; j++) {
                float vv = Vs[kk*193 + tx*12 + j];
                #pragma unroll
                for (int q = 0; q < 4; q++) acc[q][j] += pv[q]*vv;
            }
        }
        __syncthreads();
    }
    #pragma unroll
    for (int q = 0; q < 4; q++) {
        float inv = 1.f / l_run[q];
        #pragma unroll
        for (int j = 0; j < 12; j++) {
            int d = tx*12 + j;
            Ob[(long long)d*NP + n0 + tq*4 + q] = acc[q][j] * inv;
        }
    }
}

// ---------------- kNN gather + VN-leaky + mean pool -> x5 second half ----------------
__global__ __launch_bounds__(128) void gather_leaky(const float* __restrict__ G,
                                                    const int* __restrict__ knn,
                                                    float* __restrict__ X5)
{
    int bn = blockIdx.x;
    int b = bn >> 11, n = bn & 2047;
    int o = threadIdx.x;
    __shared__ int ridx[8];
    if (o < 8) ridx[o] = knn[((b*8 + o) << 11) + n];
    __syncthreads();
    const float* gc = G + (long long)bn*1536;
    float pc0 = gc[128 + o],        dc0 = gc[384 + o];
    float pc1 = gc[512 + 128 + o],  dc1 = gc[512 + 384 + o];
    float pc2 = gc[1024 + 128 + o], dc2 = gc[1024 + 384 + o];
    float a0 = 0.f, a1 = 0.f, a2 = 0.f;
    #pragma unroll
    for (int k = 0; k < 8; k++) {
        const float* gr = G + (long long)ridx[k]*1536;
        float p0 = gr[o] + pc0;
        float p1 = gr[512 + o] + pc1;
        float p2 = gr[1024 + o] + pc2;
        float d0 = gr[256 + o] + dc0;
        float d1 = gr[512 + 256 + o] + dc1;
        float d2 = gr[1024 + 256 + o] + dc2;
        float dot = p0*d0 + p1*d1 + p2*d2;
        if (dot < 0.f) {
            float f = 0.8f * dot / (d0*d0 + d1*d1 + d2*d2 + 1e-6f);
            p0 -= f*d0; p1 -= f*d1; p2 -= f*d2;
        }
        a0 += p0; a1 += p1; a2 += p2;
    }
    float* y = X5 + (long long)b*(2*NC*M3) + (long long)(128 + o)*M3 + n;
    y[0] = a0*0.125f; y[2048] = a1*0.125f; y[4096] = a2*0.125f;
}

// ---------------- elementwise VN-leaky for conv3 ----------------
__global__ void leaky_ew(const float* __restrict__ P, const float* __restrict__ D,
                         float* __restrict__ Y)
{
    int idx = blockIdx.x*256 + threadIdx.x;       // B*256*2048
    int n = idx & 2047;
    int bo = idx >> 11;
    long long base = ((long long)bo*3 << 11) + n;
    float p0 = P[base], p1 = P[base + 2048], p2 = P[base + 4096];
    float d0 = D[base], d1 = D[base + 2048], d2 = D[base + 4096];
    float dot = p0*d0 + p1*d1 + p2*d2;
    if (dot < 0.f) {
        float f = 0.8f * dot / (d0*d0 + d1*d1 + d2*d2 + 1e-6f);
        p0 -= f*d0; p1 -= f*d1; p2 -= f*d2;
    }
    Y[base] = p0; Y[base + 2048] = p1; Y[base + 4096] = p2;
}

// ---------------- conv4 leaky + residual + transpose to output ----------------
__global__ void final_k(const float* __restrict__ P, const float* __restrict__ D,
                        const float* __restrict__ vnx, float* __restrict__ out)
{
    int idx = blockIdx.x*256 + threadIdx.x;       // B*128*2048
    int n = idx & 2047;
    int o = (idx >> 11) & 127;
    int b = idx >> 18;
    long long base = ((long long)idx*3 - (long long)idx*2) ; // placeholder (unused)
    long long base2 = (((long long)(b*NC + o))*3 << 11) + n;
    float p0 = P[base2], p1 = P[base2 + 2048], p2 = P[base2 + 4096];
    float d0 = D[base2], d1 = D[base2 + 2048], d2 = D[base2 + 4096];
    float dot = p0*d0 + p1*d1 + p2*d2;
    if (dot < 0.f) {
        float f = 0.8f * dot / (d0*d0 + d1*d1 + d2*d2 + 1e-6f);
        p0 -= f*d0; p1 -= f*d1; p2 -= f*d2;
    }
    float r0 = vnx[base2], r1 = vnx[base2 + 2048], r2 = vnx[base2 + 4096];
    float* q = out + ((long long)(b*NP + n))*ND + 3*o;
    q[0] = r0 + p0; q[1] = r1 + p1; q[2] = r2 + p2;
    (void)base;
}

// ---------------- host ----------------
extern "C" void kernel_launch(void* const* d_in, const int* in_sizes, int n_in,
                              void* d_out, int out_size)
{
    (void)in_sizes; (void)n_in; (void)out_size;
    const float* x  = (const float*)d_in[0];
    const int* knn  = (const int*)d_in[1];
    const float* g1 = (const float*)d_in[2];
    const float* b1 = (const float*)d_in[3];
    const float* g2 = (const float*)d_in[4];
    const float* b2 = (const float*)d_in[5];
    const float* Wq = (const float*)d_in[6];
    const float* Wk = (const float*)d_in[7];
    const float* Wv = (const float*)d_in[8];
    const float* Wo = (const float*)d_in[9];
    const float* W1 = (const float*)d_in[10];
    const float* U1 = (const float*)d_in[11];
    const float* W2 = (const float*)d_in[12];
    const float* W3 = (const float*)d_in[13];
    const float* U3 = (const float*)d_in[14];
    const float* W4 = (const float*)d_in[15];
    const float* U4 = (const float*)d_in[16];
    float* out = (float*)d_out;

    float *normx,*q,*k,*v,*ao,*G,*x5,*vnx,*nx2,*p3,*d3,*h,*p4,*d4,*cw;
    cudaGetSymbolAddress((void**)&normx, g_normx);
    cudaGetSymbolAddress((void**)&q,  g_q);
    cudaGetSymbolAddress((void**)&k,  g_k);
    cudaGetSymbolAddress((void**)&v,  g_v);
    cudaGetSymbolAddress((void**)&ao, g_ao);
    cudaGetSymbolAddress((void**)&G,  g_G);
    cudaGetSymbolAddress((void**)&x5, g_x5);
    cudaGetSymbolAddress((void**)&vnx, g_vnx);
    cudaGetSymbolAddress((void**)&nx2, g_nx2);
    cudaGetSymbolAddress((void**)&p3, g_p3);
    cudaGetSymbolAddress((void**)&d3, g_d3);
    cudaGetSymbolAddress((void**)&h,  g_h);
    cudaGetSymbolAddress((void**)&p4, g_p4);
    cudaGetSymbolAddress((void**)&d4, g_d4);
    cudaGetSymbolAddress((void**)&cw, g_cw);

    cudaFuncSetAttribute(flash_k, cudaFuncAttributeMaxDynamicSharedMemorySize, FSMEM);

    prep_cw<<<256, 256>>>(W1, U1, cw);
    ln_k<<<NB*NP, 128>>>(x, g1, b1, normx, 0);

    long long sN = (long long)NC*M3;        // 786432
    long long sQ = (long long)ND*M3;        // per-batch q/k/v/ao stride
    long long sX5 = (long long)2*NC*M3;

    gemm_k<<<dim3(48,3,NB), 256>>>(Wq, normx, q, nullptr, 128, M3, sN, 0, sQ, 0, M3, 1, 0, 0);
    gemm_k<<<dim3(48,3,NB), 256>>>(Wk, normx, k, nullptr, 128, M3, sN, 0, sQ, 0, M3, 1, 0, 0);
    gemm_k<<<dim3(48,3,NB), 256>>>(Wv, normx, v, nullptr, 128, M3, sN, 0, sQ, 0, M3, 1, 0, 0);

    flash_k<<<dim3(32, NH, NB), 256, FSMEM>>>(q, k, v, ao);

    // Wo projection -> first half of x5
    gemm_k<<<dim3(48,1,NB), 256>>>(Wo, ao, x5, nullptr, 384, M3, sQ, 0, sX5, 0, M3, 1, 0, 0);

    // fused graph-feature GEMM: G[(b,n)][i][a*128+o]
    gemm_k<<<dim3(16,4,12), 256>>>(cw, normx, G, nullptr, 128, M3,
                                   sN, 2048, (long long)NP*1536, 512, 1, 1536, 1, 0);
    gather_leaky<<<NB*NP, 128>>>(G, knn, x5);

    // W2 @ concat + residual(x) -> vnx
    gemm_k<<<dim3(48,1,NB), 256>>>(W2, x5, vnx, x, 256, M3, sX5, 0, sN, 0, M3, 1, 0, 1);

    ln_k<<<NB*NP, 128>>>(vnx, g2, b2, nx2, 1);

    gemm_k<<<dim3(48,2,NB), 256>>>(W3, nx2, p3, nullptr, 128, M3, sN, 0, sX5, 0, M3, 1, 0, 0);
    gemm_k<<<dim3(48,2,NB), 256>>>(U3, nx2, d3, nullptr, 128, M3, sN, 0, sX5, 0, M3, 1, 0, 0);
    leaky_ew<<<NB*2*NC*NP/256, 256>>>(p3, d3, h);

    gemm_k<<<dim3(48,1,NB), 256>>>(W4, h, p4, nullptr, 256, M3, sX5, 0, sN, 0, M3, 1, 0, 0);
    gemm_k<<<dim3(48,1,NB), 256>>>(U4, h, d4, nullptr, 256, M3, sX5, 0, sN, 0, M3, 1, 0, 0);

    final_k<<<NB*NC*NP/256, 256>>>(p4, d4, vnx, out);
}

// round 3
// speedup vs baseline: 2.0786x; 2.0786x over previous
#include <cuda_runtime.h>
#include <cuda_bf16.h>
#include <math.h>

#define NB 4
#define NP 2048
#define NC 128
#define ND 384
#define NH 6
#define FD 192
#define M3 (3*NP)   // 6144

// ---------------- scratch ----------------
__device__ float g_normx[NB*NC*3*NP];
__device__ float g_q [NB*ND*3*NP];
__device__ float g_k [NB*ND*3*NP];
__device__ float g_v [NB*ND*3*NP];
__device__ float g_ao[NB*ND*3*NP];
__device__ float g_G [NB*NP*1536];
__device__ float g_x5[NB*2*NC*3*NP];
__device__ float g_vnx[NB*NC*3*NP];
__device__ float g_nx2[NB*NC*3*NP];
__device__ float g_p3[NB*2*NC*3*NP];
__device__ float g_d3[NB*2*NC*3*NP];
__device__ float g_h [NB*2*NC*3*NP];
__device__ float g_p4[NB*NC*3*NP];
__device__ float g_d4[NB*NC*3*NP];
__device__ float g_cw[512*128];

// ---------------- weight prep ----------------
__global__ void prep_cw(const float* __restrict__ W1, const float* __restrict__ U1,
                        float* __restrict__ CW)
{
    int idx = blockIdx.x * 256 + threadIdx.x;
    if (idx >= 512*128) return;
    int col = idx >> 7;
    int c   = idx & 127;
    int a = col / 128;
    int o = col % 128;
    float v;
    if      (a == 0) v = W1[o*256 + c];
    else if (a == 1) v = W1[o*256 + 128 + c] - W1[o*256 + c];
    else if (a == 2) v = U1[o*256 + c];
    else             v = U1[o*256 + 128 + c] - U1[o*256 + c];
    CW[col*128 + c] = v;
}

// ---------------- vector-norm layernorm ----------------
__global__ __launch_bounds__(128) void ln_k(const float* __restrict__ in,
                                            const float* __restrict__ g,
                                            const float* __restrict__ bb,
                                            float* __restrict__ out, int mode)
{
    int bn = blockIdx.x;
    int b = bn >> 11, n = bn & 2047;
    int c = threadIdx.x;
    float v0, v1, v2;
    if (mode == 0) {
        const float* p = in + (long long)bn*384 + 3*c;
        v0 = p[0]; v1 = p[1]; v2 = p[2];
    } else {
        const float* p = in + ((long long)b*NC + c)*M3 + n;
        v0 = p[0]; v1 = p[2048]; v2 = p[4096];
    }
    float nrm = sqrtf(v0*v0 + v1*v1 + v2*v2 + 1e-6f);
    float s = nrm, s2 = nrm*nrm;
    for (int m = 16; m; m >>= 1) {
        s  += __shfl_xor_sync(0xffffffffu, s,  m);
        s2 += __shfl_xor_sync(0xffffffffu, s2, m);
    }
    __shared__ float sb[8];
    int w = c >> 5, lane = c & 31;
    if (!lane) { sb[w] = s; sb[4 + w] = s2; }
    __syncthreads();
    float ts  = sb[0] + sb[1] + sb[2] + sb[3];
    float ts2 = sb[4] + sb[5] + sb[6] + sb[7];
    float mu  = ts * (1.f/128.f);
    float var = ts2 * (1.f/128.f) - mu*mu;
    float nhat = (nrm - mu) / sqrtf(var + 1e-5f);
    float scale = (g[c]*nhat + bb[c]) / nrm;
    float* q = out + ((long long)b*NC + c)*M3 + n;
    q[0] = v0*scale; q[2048] = v1*scale; q[4096] = v2*scale;
}

// ---------------- generic batched fp32 GEMM (unchanged) ----------------
__global__ __launch_bounds__(256) void gemm_k(
    const float* __restrict__ W, const float* __restrict__ X, float* __restrict__ Y,
    const float* __restrict__ Res,
    int Cin, int ldx,
    long long xsb, long long xsi, long long ysb, long long ysi,
    int oso, int osm, int zflag, int mode)
{
    __shared__ float sw[16*132];
    __shared__ float sx[16*128];
    int z = blockIdx.z;
    int b  = zflag ? z/3 : z;
    int i3 = zflag ? z%3 : 0;
    const float* xb = X + (long long)b*xsb + (long long)i3*xsi;
    float* yb = Y + (long long)b*ysb + (long long)i3*ysi;
    int m0 = blockIdx.x * 128;
    int o0 = blockIdx.y * 128;
    int tid = threadIdx.x;
    int to = tid >> 4, tm = tid & 15;
    float acc[8][8];
    #pragma unroll
    for (int i = 0; i < 8; i++)
        #pragma unroll
        for (int j = 0; j < 8; j++) acc[i][j] = 0.f;

    for (int k0 = 0; k0 < Cin; k0 += 16) {
        #pragma unroll
        for (int t = 0; t < 2; t++) {
            int l4 = tid + t*256;
            int row = l4 >> 2;
            int kc  = (l4 & 3) << 2;
            float4 w4 = *(const float4*)(W + (long long)(o0 + row)*Cin + k0 + kc);
            sw[(kc+0)*132 + row] = w4.x;
            sw[(kc+1)*132 + row] = w4.y;
            sw[(kc+2)*132 + row] = w4.z;
            sw[(kc+3)*132 + row] = w4.w;
        }
        #pragma unroll
        for (int t = 0; t < 2; t++) {
            int l4 = tid + t*256;
            int kr = l4 >> 5;
            int mc = (l4 & 31) << 2;
            *(float4*)(sx + kr*128 + mc) =
                *(const float4*)(xb + (long long)(k0 + kr)*ldx + m0 + mc);
        }
        __syncthreads();
        #pragma unroll
        for (int kk = 0; kk < 16; kk++) {
            float wf[8], xf[8];
            *(float4*)(wf)     = *(float4*)(sw + kk*132 + to*8);
            *(float4*)(wf + 4) = *(float4*)(sw + kk*132 + to*8 + 4);
            *(float4*)(xf)     = *(float4*)(sx + kk*128 + tm*8);
            *(float4*)(xf + 4) = *(float4*)(sx + kk*128 + tm*8 + 4);
            #pragma unroll
            for (int i = 0; i < 8; i++)
                #pragma unroll
                for (int j = 0; j < 8; j++)
                    acc[i][j] += wf[i]*xf[j];
        }
        __syncthreads();
    }

    int ob = o0 + to*8, mb = m0 + tm*8;
    if (mode == 1) {
        #pragma unroll
        for (int i = 0; i < 8; i++)
            #pragma unroll
            for (int j = 0; j < 8; j++) {
                int o = ob + i, m = mb + j;
                acc[i][j] += Res[(long long)b*NP*ND + (long long)(m & 2047)*ND + 3*o + (m >> 11)];
            }
    }
    if (osm == 1) {
        #pragma unroll
        for (int i = 0; i < 8; i++) {
            float4 v0 = make_float4(acc[i][0], acc[i][1], acc[i][2], acc[i][3]);
            float4 v1 = make_float4(acc[i][4], acc[i][5], acc[i][6], acc[i][7]);
            float* p = yb + (long long)(ob + i)*oso + mb;
            *(float4*)(p)     = v0;
            *(float4*)(p + 4) = v1;
        }
    } else if (oso == 1) {
        #pragma unroll
        for (int j = 0; j < 8; j++) {
            float4 v0 = make_float4(acc[0][j], acc[1][j], acc[2][j], acc[3][j]);
            float4 v1 = make_float4(acc[4][j], acc[5][j], acc[6][j], acc[7][j]);
            float* p = yb + (long long)(mb + j)*osm + ob;
            *(float4*)(p)     = v0;
            *(float4*)(p + 4) = v1;
        }
    } else {
        #pragma unroll
        for (int i = 0; i < 8; i++)
            #pragma unroll
            for (int j = 0; j < 8; j++)
                yb[(long long)(ob + i)*oso + (long long)(mb + j)*osm] = acc[i][j];
    }
}

// ---------------- tf32 tensor-core flash attention ----------------
// Layouts (floats): Qs[192][72], Ks[192][72], Vs[192][68], Ps[64][72] (key-major)
#define FTC_SMEM ((192*72*2 + 192*68 + 64*72 + 256)*4)

__device__ __forceinline__ unsigned f2tf(float f) {
    unsigned u;
    asm("cvt.rna.tf32.f32 %0, %1;" : "=r"(u) : "f"(f));
    return u;
}
__device__ __forceinline__ void mma8(float* d, const unsigned* a, unsigned b0, unsigned b1) {
    asm volatile("mma.sync.aligned.m16n8k8.row.col.f32.tf32.tf32.f32 "
                 "{%0,%1,%2,%3},{%4,%5,%6,%7},{%8,%9},{%0,%1,%2,%3};"
                 : "+f"(d[0]), "+f"(d[1]), "+f"(d[2]), "+f"(d[3])
                 : "r"(a[0]), "r"(a[1]), "r"(a[2]), "r"(a[3]), "r"(b0), "r"(b1));
}

__global__ __launch_bounds__(128) void flash_tc(const float* __restrict__ Q,
                                                const float* __restrict__ K,
                                                const float* __restrict__ V,
                                                float* __restrict__ O)
{
    extern __shared__ float sm[];
    float* Qs = sm;                    // [192][72]
    float* Ks = Qs + 192*72;           // [192][72]
    float* Vs = Ks + 192*72;           // [192][68]
    float* Ps = Vs + 192*68;           // [64][72]
    float* red  = Ps + 64*72;          // [128] row max slots
    float* red2 = red + 128;           // [128] row sum slots

    int n0 = blockIdx.x * 64;
    long long hb = (long long)(blockIdx.z*NH + blockIdx.y) * FD * NP;
    const float* Qb = Q + hb;
    const float* Kb = K + hb;
    const float* Vb = V + hb;
    float* Ob = O + hb;

    int tid = threadIdx.x;
    int wid = tid >> 5, lane = tid & 31;
    int mg = wid >> 1, half = wid & 1;
    int qb_ = mg * 32;            // query base within 64-row tile
    int kb_ = half * 32;          // key base within 64-key tile (for QK)
    int db_ = half * 96;          // d base (for PV)
    int a_ = lane >> 2, b_ = lane & 3;

    // load Q tile (prescaled by softmax scale, rounded to tf32)
    for (int idx = tid; idx < 192*16; idx += 128) {
        int d = idx >> 4, c = (idx & 15) << 2;
        float4 v = *(const float4*)(Qb + (long long)d*NP + n0 + c);
        unsigned q0 = f2tf(v.x*0.125f), q1 = f2tf(v.y*0.125f);
        unsigned q2 = f2tf(v.z*0.125f), q3 = f2tf(v.w*0.125f);
        float4 w = make_float4(__uint_as_float(q0), __uint_as_float(q1),
                               __uint_as_float(q2), __uint_as_float(q3));
        *(float4*)(Qs + d*72 + c) = w;
    }

    float o_acc[2][12][4];
    #pragma unroll
    for (int mf = 0; mf < 2; mf++)
        #pragma unroll
        for (int nd = 0; nd < 12; nd++)
            #pragma unroll
            for (int c = 0; c < 4; c++) o_acc[mf][nd][c] = 0.f;
    float m_run[4] = {-1e30f, -1e30f, -1e30f, -1e30f};
    float l_run[4] = {0.f, 0.f, 0.f, 0.f};

    for (int kt = 0; kt < NP; kt += 64) {
        __syncthreads();
        // load K/V tiles (tf32-rounded)
        for (int idx = tid; idx < 192*16; idx += 128) {
            int d = idx >> 4, c = (idx & 15) << 2;
            float4 v = *(const float4*)(Kb + (long long)d*NP + kt + c);
            v.x = __uint_as_float(f2tf(v.x)); v.y = __uint_as_float(f2tf(v.y));
            v.z = __uint_as_float(f2tf(v.z)); v.w = __uint_as_float(f2tf(v.w));
            *(float4*)(Ks + d*72 + c) = v;
            float4 u = *(const float4*)(Vb + (long long)d*NP + kt + c);
            u.x = __uint_as_float(f2tf(u.x)); u.y = __uint_as_float(f2tf(u.y));
            u.z = __uint_as_float(f2tf(u.z)); u.w = __uint_as_float(f2tf(u.w));
            *(float4*)(Vs + d*68 + c) = u;
        }
        __syncthreads();

        // ---- QK^T: S[32 q][32 k] per warp ----
        float s[2][4][4];
        #pragma unroll
        for (int mf = 0; mf < 2; mf++)
            #pragma unroll
            for (int nf = 0; nf < 4; nf++)
                #pragma unroll
                for (int c = 0; c < 4; c++) s[mf][nf][c] = 0.f;

        #pragma unroll
        for (int kf = 0; kf < 24; kf++) {
            const float* qp = Qs + (kf*8 + b_)*72 + qb_ + a_;
            unsigned A[2][4];
            A[0][0] = __float_as_uint(qp[0]);   A[0][1] = __float_as_uint(qp[8]);
            A[0][2] = __float_as_uint(qp[288]); A[0][3] = __float_as_uint(qp[296]);
            A[1][0] = __float_as_uint(qp[16]);  A[1][1] = __float_as_uint(qp[24]);
            A[1][2] = __float_as_uint(qp[304]); A[1][3] = __float_as_uint(qp[312]);
            const float* kp = Ks + (kf*8 + b_)*72 + kb_ + a_;
            #pragma unroll
            for (int nf = 0; nf < 4; nf++) {
                unsigned B0 = __float_as_uint(kp[nf*8]);
                unsigned B1 = __float_as_uint(kp[nf*8 + 288]);
                mma8(s[0][nf], A[0], B0, B1);
                mma8(s[1][nf], A[1], B0, B1);
            }
        }

        // ---- online softmax ----
        float mx[4];
        #pragma unroll
        for (int r = 0; r < 4; r++) {
            int mf = r >> 1, hi = (r & 1) << 1;
            float m0 = fmaxf(fmaxf(s[mf][0][hi], s[mf][0][hi+1]),
                             fmaxf(s[mf][1][hi], s[mf][1][hi+1]));
            float m1 = fmaxf(fmaxf(s[mf][2][hi], s[mf][2][hi+1]),
                             fmaxf(s[mf][3][hi], s[mf][3][hi+1]));
            float m = fmaxf(m0, m1);
            m = fmaxf(m, __shfl_xor_sync(0xffffffffu, m, 1));
            m = fmaxf(m, __shfl_xor_sync(0xffffffffu, m, 2));
            mx[r] = m;
        }
        if (b_ == 0) {
            #pragma unroll
            for (int r = 0; r < 4; r++)
                red[(qb_ + a_ + r*8)*2 + half] = mx[r];
        }
        __syncthreads();
        float alpha[4];
        #pragma unroll
        for (int r = 0; r < 4; r++) {
            int row = qb_ + a_ + r*8;
            float tmx = fmaxf(red[row*2], red[row*2 + 1]);
            float mn = fmaxf(m_run[r], tmx);
            alpha[r] = __expf(m_run[r] - mn);
            m_run[r] = mn;
        }
        float psum[4] = {0.f, 0.f, 0.f, 0.f};
        #pragma unroll
        for (int mf = 0; mf < 2; mf++)
            #pragma unroll
            for (int nf = 0; nf < 4; nf++)
                #pragma unroll
                for (int c = 0; c < 4; c++) {
                    int r = mf*2 + (c >> 1);
                    float p = __expf(s[mf][nf][c] - m_run[r]);
                    psum[r] += p;
                    int key = kb_ + nf*8 + 2*b_ + (c & 1);
                    int row = qb_ + mf*16 + a_ + ((c >> 1) ? 8 : 0);
                    Ps[key*72 + row] = p;
                }
        #pragma unroll
        for (int r = 0; r < 4; r++) {
            float ps = psum[r];
            ps += __shfl_xor_sync(0xffffffffu, ps, 1);
            ps += __shfl_xor_sync(0xffffffffu, ps, 2);
            if (b_ == 0) red2[(qb_ + a_ + r*8)*2 + half] = ps;
        }
        __syncthreads();
        #pragma unroll
        for (int r = 0; r < 4; r++) {
            int row = qb_ + a_ + r*8;
            l_run[r] = l_run[r]*alpha[r] + red2[row*2] + red2[row*2 + 1];
        }
        #pragma unroll
        for (int mf = 0; mf < 2; mf++)
            #pragma unroll
            for (int nd = 0; nd < 12; nd++) {
                o_acc[mf][nd][0] *= alpha[mf*2];
                o_acc[mf][nd][1] *= alpha[mf*2];
                o_acc[mf][nd][2] *= alpha[mf*2 + 1];
                o_acc[mf][nd][3] *= alpha[mf*2 + 1];
            }

        // ---- PV: O[32 q][96 d] per warp ----
        #pragma unroll
        for (int kf = 0; kf < 8; kf++) {
            const float* pp = Ps + (kf*8 + b_)*72 + qb_ + a_;
            unsigned A[2][4];
            A[0][0] = __float_as_uint(pp[0]);   A[0][1] = __float_as_uint(pp[8]);
            A[0][2] = __float_as_uint(pp[288]); A[0][3] = __float_as_uint(pp[296]);
            A[1][0] = __float_as_uint(pp[16]);  A[1][1] = __float_as_uint(pp[24]);
            A[1][2] = __float_as_uint(pp[304]); A[1][3] = __float_as_uint(pp[312]);
            const float* vp = Vs + (db_ + a_)*68 + kf*8 + b_;
            #pragma unroll
            for (int nd = 0; nd < 12; nd++) {
                unsigned B0 = __float_as_uint(vp[nd*8*68]);
                unsigned B1 = __float_as_uint(vp[nd*8*68 + 4]);
                mma8(o_acc[0][nd], A[0], B0, B1);
                mma8(o_acc[1][nd], A[1], B0, B1);
            }
        }
    }

    // epilogue
    float inv[4];
    #pragma unroll
    for (int r = 0; r < 4; r++) inv[r] = 1.f / l_run[r];
    #pragma unroll
    for (int mf = 0; mf < 2; mf++)
        #pragma unroll
        for (int nd = 0; nd < 12; nd++)
            #pragma unroll
            for (int c = 0; c < 4; c++) {
                int d = db_ + nd*8 + 2*b_ + (c & 1);
                int row = n0 + qb_ + mf*16 + a_ + ((c >> 1) ? 8 : 0);
                Ob[(long long)d*NP + row] = o_acc[mf][nd][c] * inv[mf*2 + (c >> 1)];
            }
}

// ---------------- kNN gather + VN-leaky + mean pool ----------------
__global__ __launch_bounds__(128) void gather_leaky(const float* __restrict__ G,
                                                    const int* __restrict__ knn,
                                                    float* __restrict__ X5)
{
    int bn = blockIdx.x;
    int b = bn >> 11, n = bn & 2047;
    int o = threadIdx.x;
    __shared__ int ridx[8];
    if (o < 8) ridx[o] = knn[((b*8 + o) << 11) + n];
    __syncthreads();
    const float* gc = G + (long long)bn*1536;
    float pc0 = gc[128 + o],        dc0 = gc[384 + o];
    float pc1 = gc[512 + 128 + o],  dc1 = gc[512 + 384 + o];
    float pc2 = gc[1024 + 128 + o], dc2 = gc[1024 + 384 + o];
    float a0 = 0.f, a1 = 0.f, a2 = 0.f;
    #pragma unroll
    for (int k = 0; k < 8; k++) {
        const float* gr = G + (long long)ridx[k]*1536;
        float p0 = gr[o] + pc0;
        float p1 = gr[512 + o] + pc1;
        float p2 = gr[1024 + o] + pc2;
        float d0 = gr[256 + o] + dc0;
        float d1 = gr[512 + 256 + o] + dc1;
        float d2 = gr[1024 + 256 + o] + dc2;
        float dot = p0*d0 + p1*d1 + p2*d2;
        if (dot < 0.f) {
            float f = 0.8f * dot / (d0*d0 + d1*d1 + d2*d2 + 1e-6f);
            p0 -= f*d0; p1 -= f*d1; p2 -= f*d2;
        }
        a0 += p0; a1 += p1; a2 += p2;
    }
    float* y = X5 + (long long)b*(2*NC*M3) + (long long)(128 + o)*M3 + n;
    y[0] = a0*0.125f; y[2048] = a1*0.125f; y[4096] = a2*0.125f;
}

// ---------------- elementwise VN-leaky ----------------
__global__ void leaky_ew(const float* __restrict__ P, const float* __restrict__ D,
                         float* __restrict__ Y)
{
    int idx = blockIdx.x*256 + threadIdx.x;
    int n = idx & 2047;
    int bo = idx >> 11;
    long long base = ((long long)bo*3 << 11) + n;
    float p0 = P[base], p1 = P[base + 2048], p2 = P[base + 4096];
    float d0 = D[base], d1 = D[base + 2048], d2 = D[base + 4096];
    float dot = p0*d0 + p1*d1 + p2*d2;
    if (dot < 0.f) {
        float f = 0.8f * dot / (d0*d0 + d1*d1 + d2*d2 + 1e-6f);
        p0 -= f*d0; p1 -= f*d1; p2 -= f*d2;
    }
    Y[base] = p0; Y[base + 2048] = p1; Y[base + 4096] = p2;
}

// ---------------- conv4 leaky + residual + output transpose ----------------
__global__ void final_k(const float* __restrict__ P, const float* __restrict__ D,
                        const float* __restrict__ vnx, float* __restrict__ out)
{
    int idx = blockIdx.x*256 + threadIdx.x;
    int n = idx & 2047;
    int o = (idx >> 11) & 127;
    int b = idx >> 18;
    long long base2 = (((long long)(b*NC + o))*3 << 11) + n;
    float p0 = P[base2], p1 = P[base2 + 2048], p2 = P[base2 + 4096];
    float d0 = D[base2], d1 = D[base2 + 2048], d2 = D[base2 + 4096];
    float dot = p0*d0 + p1*d1 + p2*d2;
    if (dot < 0.f) {
        float f = 0.8f * dot / (d0*d0 + d1*d1 + d2*d2 + 1e-6f);
        p0 -= f*d0; p1 -= f*d1; p2 -= f*d2;
    }
    float r0 = vnx[base2], r1 = vnx[base2 + 2048], r2 = vnx[base2 + 4096];
    float* q = out + ((long long)(b*NP + n))*ND + 3*o;
    q[0] = r0 + p0; q[1] = r1 + p1; q[2] = r2 + p2;
}

// ---------------- host ----------------
extern "C" void kernel_launch(void* const* d_in, const int* in_sizes, int n_in,
                              void* d_out, int out_size)
{
    (void)in_sizes; (void)n_in; (void)out_size;
    const float* x  = (const float*)d_in[0];
    const int* knn  = (const int*)d_in[1];
    const float* g1 = (const float*)d_in[2];
    const float* b1 = (const float*)d_in[3];
    const float* g2 = (const float*)d_in[4];
    const float* b2 = (const float*)d_in[5];
    const float* Wq = (const float*)d_in[6];
    const float* Wk = (const float*)d_in[7];
    const float* Wv = (const float*)d_in[8];
    const float* Wo = (const float*)d_in[9];
    const float* W1 = (const float*)d_in[10];
    const float* U1 = (const float*)d_in[11];
    const float* W2 = (const float*)d_in[12];
    const float* W3 = (const float*)d_in[13];
    const float* U3 = (const float*)d_in[14];
    const float* W4 = (const float*)d_in[15];
    const float* U4 = (const float*)d_in[16];
    float* out = (float*)d_out;

    float *normx,*q,*k,*v,*ao,*G,*x5,*vnx,*nx2,*p3,*d3,*h,*p4,*d4,*cw;
    cudaGetSymbolAddress((void**)&normx, g_normx);
    cudaGetSymbolAddress((void**)&q,  g_q);
    cudaGetSymbolAddress((void**)&k,  g_k);
    cudaGetSymbolAddress((void**)&v,  g_v);
    cudaGetSymbolAddress((void**)&ao, g_ao);
    cudaGetSymbolAddress((void**)&G,  g_G);
    cudaGetSymbolAddress((void**)&x5, g_x5);
    cudaGetSymbolAddress((void**)&vnx, g_vnx);
    cudaGetSymbolAddress((void**)&nx2, g_nx2);
    cudaGetSymbolAddress((void**)&p3, g_p3);
    cudaGetSymbolAddress((void**)&d3, g_d3);
    cudaGetSymbolAddress((void**)&h,  g_h);
    cudaGetSymbolAddress((void**)&p4, g_p4);
    cudaGetSymbolAddress((void**)&d4, g_d4);
    cudaGetSymbolAddress((void**)&cw, g_cw);

    cudaFuncSetAttribute(flash_tc, cudaFuncAttributeMaxDynamicSharedMemorySize, FTC_SMEM);

    prep_cw<<<256, 256>>>(W1, U1, cw);
    ln_k<<<NB*NP, 128>>>(x, g1, b1, normx, 0);

    long long sN = (long long)NC*M3;
    long long sQ = (long long)ND*M3;
    long long sX5 = (long long)2*NC*M3;

    gemm_k<<<dim3(48,3,NB), 256>>>(Wq, normx, q, nullptr, 128, M3, sN, 0, sQ, 0, M3, 1, 0, 0);
    gemm_k<<<dim3(48,3,NB), 256>>>(Wk, normx, k, nullptr, 128, M3, sN, 0, sQ, 0, M3, 1, 0, 0);
    gemm_k<<<dim3(48,3,NB), 256>>>(Wv, normx, v, nullptr, 128, M3, sN, 0, sQ, 0, M3, 1, 0, 0);

    flash_tc<<<dim3(32, NH, NB), 128, FTC_SMEM>>>(q, k, v, ao);

    gemm_k<<<dim3(48,1,NB), 256>>>(Wo, ao, x5, nullptr, 384, M3, sQ, 0, sX5, 0, M3, 1, 0, 0);

    gemm_k<<<dim3(16,4,12), 256>>>(cw, normx, G, nullptr, 128, M3,
                                   sN, 2048, (long long)NP*1536, 512, 1, 1536, 1, 0);
    gather_leaky<<<NB*NP, 128>>>(G, knn, x5);

    gemm_k<<<dim3(48,1,NB), 256>>>(W2, x5, vnx, x, 256, M3, sX5, 0, sN, 0, M3, 1, 0, 1);

    ln_k<<<NB*NP, 128>>>(vnx, g2, b2, nx2, 1);

    gemm_k<<<dim3(48,2,NB), 256>>>(W3, nx2, p3, nullptr, 128, M3, sN, 0, sX5, 0, M3, 1, 0, 0);
    gemm_k<<<dim3(48,2,NB), 256>>>(U3, nx2, d3, nullptr, 128, M3, sN, 0, sX5, 0, M3, 1, 0, 0);
    leaky_ew<<<NB*2*NC*NP/256, 256>>>(p3, d3, h);

    gemm_k<<<dim3(48,1,NB), 256>>>(W4, h, p4, nullptr, 256, M3, sX5, 0, sN, 0, M3, 1, 0, 0);
    gemm_k<<<dim3(48,1,NB), 256>>>(U4, h, d4, nullptr, 256, M3, sX5, 0, sN, 0, M3, 1, 0, 0);

    final_k<<<NB*NC*NP/256, 256>>>(p4, d4, vnx, out);
}

// round 4
// speedup vs baseline: 2.6079x; 1.2546x over previous
#include <cuda_runtime.h>
#include <cuda_bf16.h>
#include <math.h>

#define NB 4
#define NP 2048
#define NC 128
#define ND 384
#define NH 6
#define FD 192
#define M3 (3*NP)   // 6144

// ---------------- scratch ----------------
__device__ float g_normx[NB*NC*3*NP];
__device__ float g_q [NB*ND*3*NP];
__device__ float g_k [NB*ND*3*NP];
__device__ float g_v [NB*ND*3*NP];
__device__ float g_ao[NB*ND*3*NP];
__device__ float g_G [NB*NP*1536];
__device__ float g_x5[NB*2*NC*3*NP];
__device__ float g_vnx[NB*NC*3*NP];
__device__ float g_nx2[NB*NC*3*NP];
__device__ float g_p3[NB*2*NC*3*NP];
__device__ float g_d3[NB*2*NC*3*NP];
__device__ float g_h [NB*2*NC*3*NP];
__device__ float g_p4[NB*NC*3*NP];
__device__ float g_d4[NB*NC*3*NP];
__device__ float g_cw[512*128];

__device__ __forceinline__ unsigned f2tf(float f) {
    unsigned u;
    asm("cvt.rna.tf32.f32 %0, %1;" : "=r"(u) : "f"(f));
    return u;
}
__device__ __forceinline__ void mma8(float* d, const unsigned* a, unsigned b0, unsigned b1) {
    asm volatile("mma.sync.aligned.m16n8k8.row.col.f32.tf32.tf32.f32 "
                 "{%0,%1,%2,%3},{%4,%5,%6,%7},{%8,%9},{%0,%1,%2,%3};"
                 : "+f"(d[0]), "+f"(d[1]), "+f"(d[2]), "+f"(d[3])
                 : "r"(a[0]), "r"(a[1]), "r"(a[2]), "r"(a[3]), "r"(b0), "r"(b1));
}

// ---------------- weight prep ----------------
__global__ void prep_cw(const float* __restrict__ W1, const float* __restrict__ U1,
                        float* __restrict__ CW)
{
    int idx = blockIdx.x * 256 + threadIdx.x;
    if (idx >= 512*128) return;
    int col = idx >> 7;
    int c   = idx & 127;
    int a = col / 128;
    int o = col % 128;
    float v;
    if      (a == 0) v = W1[o*256 + c];
    else if (a == 1) v = W1[o*256 + 128 + c] - W1[o*256 + c];
    else if (a == 2) v = U1[o*256 + c];
    else             v = U1[o*256 + 128 + c] - U1[o*256 + c];
    CW[col*128 + c] = v;
}

// ---------------- vector-norm layernorm ----------------
__global__ __launch_bounds__(128) void ln_k(const float* __restrict__ in,
                                            const float* __restrict__ g,
                                            const float* __restrict__ bb,
                                            float* __restrict__ out, int mode)
{
    int bn = blockIdx.x;
    int b = bn >> 11, n = bn & 2047;
    int c = threadIdx.x;
    float v0, v1, v2;
    if (mode == 0) {
        const float* p = in + (long long)bn*384 + 3*c;
        v0 = p[0]; v1 = p[1]; v2 = p[2];
    } else {
        const float* p = in + ((long long)b*NC + c)*M3 + n;
        v0 = p[0]; v1 = p[2048]; v2 = p[4096];
    }
    float nrm = sqrtf(v0*v0 + v1*v1 + v2*v2 + 1e-6f);
    float s = nrm, s2 = nrm*nrm;
    for (int m = 16; m; m >>= 1) {
        s  += __shfl_xor_sync(0xffffffffu, s,  m);
        s2 += __shfl_xor_sync(0xffffffffu, s2, m);
    }
    __shared__ float sb[8];
    int w = c >> 5, lane = c & 31;
    if (!lane) { sb[w] = s; sb[4 + w] = s2; }
    __syncthreads();
    float ts  = sb[0] + sb[1] + sb[2] + sb[3];
    float ts2 = sb[4] + sb[5] + sb[6] + sb[7];
    float mu  = ts * (1.f/128.f);
    float var = ts2 * (1.f/128.f) - mu*mu;
    float nhat = (nrm - mu) / sqrtf(var + 1e-5f);
    float scale = (g[c]*nhat + bb[c]) / nrm;
    float* q = out + ((long long)b*NC + c)*M3 + n;
    q[0] = v0*scale; q[2048] = v1*scale; q[4096] = v2*scale;
}

// ---------------- tf32 tensor-core batched GEMM ----------------
// Y[o,m] = sum_c W[o,c] * X[c*ldx + m]. Tiles 128x128, BK=16, 8 warps.
__global__ __launch_bounds__(256) void gemm_k(
    const float* __restrict__ W, const float* __restrict__ X, float* __restrict__ Y,
    const float* __restrict__ Res,
    int Cin, int ldx,
    long long xsb, long long xsi, long long ysb, long long ysi,
    int oso, int osm, int zflag, int mode)
{
    __shared__ float sw[16*136];
    __shared__ float sx[16*136];
    int z = blockIdx.z;
    int b  = zflag ? z/3 : z;
    int i3 = zflag ? z%3 : 0;
    const float* xb = X + (long long)b*xsb + (long long)i3*xsi;
    float* yb = Y + (long long)b*ysb + (long long)i3*ysi;
    int m0 = blockIdx.x * 128;
    int o0 = blockIdx.y * 128;
    int tid = threadIdx.x;
    int wid = tid >> 5, lane = tid & 31;
    int a_ = lane >> 2, b_ = lane & 3;
    int wy = wid >> 1, wx = wid & 1;        // o-group(32), m-group(64)

    float acc[2][8][4];
    #pragma unroll
    for (int i = 0; i < 2; i++)
        #pragma unroll
        for (int j = 0; j < 8; j++)
            #pragma unroll
            for (int c = 0; c < 4; c++) acc[i][j][c] = 0.f;

    for (int k0 = 0; k0 < Cin; k0 += 16) {
        #pragma unroll
        for (int t = 0; t < 2; t++) {
            int l4 = tid + t*256;
            int row = l4 >> 2;
            int kc  = (l4 & 3) << 2;
            float4 w4 = *(const float4*)(W + (long long)(o0 + row)*Cin + k0 + kc);
            sw[(kc+0)*136 + row] = __uint_as_float(f2tf(w4.x));
            sw[(kc+1)*136 + row] = __uint_as_float(f2tf(w4.y));
            sw[(kc+2)*136 + row] = __uint_as_float(f2tf(w4.z));
            sw[(kc+3)*136 + row] = __uint_as_float(f2tf(w4.w));
        }
        #pragma unroll
        for (int t = 0; t < 2; t++) {
            int l4 = tid + t*256;
            int kr = l4 >> 5;
            int mc = (l4 & 31) << 2;
            float4 x4 = *(const float4*)(xb + (long long)(k0 + kr)*ldx + m0 + mc);
            x4.x = __uint_as_float(f2tf(x4.x)); x4.y = __uint_as_float(f2tf(x4.y));
            x4.z = __uint_as_float(f2tf(x4.z)); x4.w = __uint_as_float(f2tf(x4.w));
            *(float4*)(sx + kr*136 + mc) = x4;
        }
        __syncthreads();
        #pragma unroll
        for (int kf = 0; kf < 2; kf++) {
            const float* wp = sw + (kf*8 + b_)*136 + wy*32 + a_;
            unsigned A[2][4];
            A[0][0] = __float_as_uint(wp[0]);   A[0][1] = __float_as_uint(wp[8]);
            A[0][2] = __float_as_uint(wp[544]); A[0][3] = __float_as_uint(wp[552]);
            A[1][0] = __float_as_uint(wp[16]);  A[1][1] = __float_as_uint(wp[24]);
            A[1][2] = __float_as_uint(wp[560]); A[1][3] = __float_as_uint(wp[568]);
            const float* xp = sx + (kf*8 + b_)*136 + wx*64 + a_;
            #pragma unroll
            for (int nf = 0; nf < 8; nf++) {
                unsigned B0 = __float_as_uint(xp[nf*8]);
                unsigned B1 = __float_as_uint(xp[nf*8 + 544]);
                mma8(acc[0][nf], A[0], B0, B1);
                mma8(acc[1][nf], A[1], B0, B1);
            }
        }
        __syncthreads();
    }

    int ob = o0 + wy*32, mb = m0 + wx*64;
    if (osm == 1) {
        #pragma unroll
        for (int mf = 0; mf < 2; mf++)
            #pragma unroll
            for (int nf = 0; nf < 8; nf++) {
                int o = ob + mf*16 + a_;
                int m = mb + nf*8 + 2*b_;
                float2 v0 = make_float2(acc[mf][nf][0], acc[mf][nf][1]);
                float2 v1 = make_float2(acc[mf][nf][2], acc[mf][nf][3]);
                if (mode == 1) {
                    long long rb = (long long)b*NP*ND;
                    v0.x += Res[rb + (long long)(m & 2047)*ND + 3*o + (m >> 11)];
                    v0.y += Res[rb + (long long)((m+1) & 2047)*ND + 3*o + ((m+1) >> 11)];
                    v1.x += Res[rb + (long long)(m & 2047)*ND + 3*(o+8) + (m >> 11)];
                    v1.y += Res[rb + (long long)((m+1) & 2047)*ND + 3*(o+8) + ((m+1) >> 11)];
                }
                *(float2*)(yb + (long long)o*oso + m) = v0;
                *(float2*)(yb + (long long)(o+8)*oso + m) = v1;
            }
    } else {
        #pragma unroll
        for (int mf = 0; mf < 2; mf++)
            #pragma unroll
            for (int nf = 0; nf < 8; nf++)
                #pragma unroll
                for (int c = 0; c < 4; c++) {
                    int o = ob + mf*16 + a_ + ((c >> 1) ? 8 : 0);
                    int m = mb + nf*8 + 2*b_ + (c & 1);
                    yb[(long long)o*oso + (long long)m*osm] = acc[mf][nf][c];
                }
    }
}

// ---------------- tf32 flash attention v2: 128q tile, 32-key stream, 8 warps ----------------
// Qs[192][136], Ks[192][40], Vs[192][40], Ps[32][136], state arrays
#define FTC_SMEM ((192*136 + 192*40*2 + 32*136 + 896)*4)

__global__ __launch_bounds__(256) void flash_tc(const float* __restrict__ Q,
                                                const float* __restrict__ K,
                                                const float* __restrict__ V,
                                                float* __restrict__ O)
{
    extern __shared__ float sm[];
    float* Qs = sm;                     // [192][136]
    float* Ks = Qs + 192*136;           // [192][40]
    float* Vs = Ks + 192*40;            // [192][40]
    float* Ps = Vs + 192*40;            // [32 keys][136 rows]
    float* m_s  = Ps + 32*136;          // [128]
    float* l_s  = m_s + 128;            // [128]
    float* al_s = l_s + 128;            // [128]
    float* red  = al_s + 128;           // [256]
    float* red2 = red + 256;            // [256]

    int n0 = blockIdx.x * 128;
    long long hb = (long long)(blockIdx.z*NH + blockIdx.y) * FD * NP;
    const float* Qb = Q + hb;
    const float* Kb = K + hb;
    const float* Vb = V + hb;
    float* Ob = O + hb;

    int tid = threadIdx.x;
    int wid = tid >> 5, lane = tid & 31;
    int a_ = lane >> 2, b_ = lane & 3;
    int qg = wid >> 1, kh = wid & 1;    // QK: 32q x 16k per warp
    int db = wid * 24;                  // PV: 24-dim slice per warp

    // load Q (prescaled, tf32)
    for (int idx = tid; idx < 192*32; idx += 256) {
        int d = idx >> 5, c = (idx & 31) << 2;
        float4 v = *(const float4*)(Qb + (long long)d*NP + n0 + c);
        v.x = __uint_as_float(f2tf(v.x*0.125f)); v.y = __uint_as_float(f2tf(v.y*0.125f));
        v.z = __uint_as_float(f2tf(v.z*0.125f)); v.w = __uint_as_float(f2tf(v.w*0.125f));
        *(float4*)(Qs + d*136 + c) = v;
    }
    if (tid < 128) { m_s[tid] = -1e30f; l_s[tid] = 0.f; }

    float o_acc[8][3][4];
    #pragma unroll
    for (int i = 0; i < 8; i++)
        #pragma unroll
        for (int j = 0; j < 3; j++)
            #pragma unroll
            for (int c = 0; c < 4; c++) o_acc[i][j][c] = 0.f;

    for (int kt = 0; kt < NP; kt += 32) {
        __syncthreads();
        for (int idx = tid; idx < 192*8; idx += 256) {
            int d = idx >> 3, c = (idx & 7) << 2;
            float4 v = *(const float4*)(Kb + (long long)d*NP + kt + c);
            v.x = __uint_as_float(f2tf(v.x)); v.y = __uint_as_float(f2tf(v.y));
            v.z = __uint_as_float(f2tf(v.z)); v.w = __uint_as_float(f2tf(v.w));
            *(float4*)(Ks + d*40 + c) = v;
            float4 u = *(const float4*)(Vb + (long long)d*NP + kt + c);
            u.x = __uint_as_float(f2tf(u.x)); u.y = __uint_as_float(f2tf(u.y));
            u.z = __uint_as_float(f2tf(u.z)); u.w = __uint_as_float(f2tf(u.w));
            *(float4*)(Vs + d*40 + c) = u;
        }
        __syncthreads();

        // ---- QK: 32q x 16k per warp ----
        float s[2][2][4];
        #pragma unroll
        for (int mf = 0; mf < 2; mf++)
            #pragma unroll
            for (int nf = 0; nf < 2; nf++)
                #pragma unroll
                for (int c = 0; c < 4; c++) s[mf][nf][c] = 0.f;
        #pragma unroll
        for (int kf = 0; kf < 24; kf++) {
            const float* qp = Qs + (kf*8 + b_)*136 + qg*32 + a_;
            unsigned A[2][4];
            A[0][0] = __float_as_uint(qp[0]);   A[0][1] = __float_as_uint(qp[8]);
            A[0][2] = __float_as_uint(qp[544]); A[0][3] = __float_as_uint(qp[552]);
            A[1][0] = __float_as_uint(qp[16]);  A[1][1] = __float_as_uint(qp[24]);
            A[1][2] = __float_as_uint(qp[560]); A[1][3] = __float_as_uint(qp[568]);
            const float* kp = Ks + (kf*8 + b_)*40 + kh*16 + a_;
            #pragma unroll
            for (int nf = 0; nf < 2; nf++) {
                unsigned B0 = __float_as_uint(kp[nf*8]);
                unsigned B1 = __float_as_uint(kp[nf*8 + 160]);
                mma8(s[0][nf], A[0], B0, B1);
                mma8(s[1][nf], A[1], B0, B1);
            }
        }

        // ---- row max ----
        #pragma unroll
        for (int r = 0; r < 4; r++) {
            int mf = r >> 1, hi = (r & 1) << 1;
            float m = fmaxf(fmaxf(s[mf][0][hi], s[mf][0][hi+1]),
                            fmaxf(s[mf][1][hi], s[mf][1][hi+1]));
            m = fmaxf(m, __shfl_xor_sync(0xffffffffu, m, 1));
            m = fmaxf(m, __shfl_xor_sync(0xffffffffu, m, 2));
            if (b_ == 0)
                red[(qg*32 + mf*16 + a_ + (r & 1)*8)*2 + kh] = m;
        }
        __syncthreads();
        if (tid < 128) {
            float tm = fmaxf(red[tid*2], red[tid*2 + 1]);
            float mn = fmaxf(m_s[tid], tm);
            al_s[tid] = __expf(m_s[tid] - mn);
            m_s[tid] = mn;
        }
        __syncthreads();

        // ---- exp + Ps + psum; rescale o_acc ----
        float psum[4] = {0.f, 0.f, 0.f, 0.f};
        #pragma unroll
        for (int mf = 0; mf < 2; mf++)
            #pragma unroll
            for (int c2 = 0; c2 < 2; c2++) {
                int row = qg*32 + mf*16 + a_ + c2*8;
                float mrow = m_s[row];
                #pragma unroll
                for (int nf = 0; nf < 2; nf++)
                    #pragma unroll
                    for (int c1 = 0; c1 < 2; c1++) {
                        float p = __expf(s[mf][nf][c2*2 + c1] - mrow);
                        psum[mf*2 + c2] += p;
                        Ps[(kh*16 + nf*8 + 2*b_ + c1)*136 + row] = p;
                    }
            }
        #pragma unroll
        for (int r = 0; r < 4; r++) {
            float ps = psum[r];
            ps += __shfl_xor_sync(0xffffffffu, ps, 1);
            ps += __shfl_xor_sync(0xffffffffu, ps, 2);
            if (b_ == 0)
                red2[(qg*32 + (r >> 1)*16 + a_ + (r & 1)*8)*2 + kh] = ps;
        }
        #pragma unroll
        for (int mf8 = 0; mf8 < 8; mf8++) {
            float al0 = al_s[mf8*16 + a_];
            float al1 = al_s[mf8*16 + a_ + 8];
            #pragma unroll
            for (int nd = 0; nd < 3; nd++) {
                o_acc[mf8][nd][0] *= al0; o_acc[mf8][nd][1] *= al0;
                o_acc[mf8][nd][2] *= al1; o_acc[mf8][nd][3] *= al1;
            }
        }
        __syncthreads();
        if (tid < 128)
            l_s[tid] = l_s[tid]*al_s[tid] + red2[tid*2] + red2[tid*2 + 1];

        // ---- PV: all 128 q x 24-dim slice ----
        #pragma unroll
        for (int kf = 0; kf < 4; kf++) {
            unsigned Bv[3][2];
            #pragma unroll
            for (int nd = 0; nd < 3; nd++) {
                const float* vp = Vs + (db + nd*8 + a_)*40 + kf*8 + b_;
                Bv[nd][0] = __float_as_uint(vp[0]);
                Bv[nd][1] = __float_as_uint(vp[4]);
            }
            const float* pp = Ps + (kf*8 + b_)*136 + a_;
            #pragma unroll
            for (int mf8 = 0; mf8 < 8; mf8++) {
                unsigned A4[4];
                A4[0] = __float_as_uint(pp[mf8*16]);
                A4[1] = __float_as_uint(pp[mf8*16 + 8]);
                A4[2] = __float_as_uint(pp[mf8*16 + 544]);
                A4[3] = __float_as_uint(pp[mf8*16 + 552]);
                mma8(o_acc[mf8][0], A4, Bv[0][0], Bv[0][1]);
                mma8(o_acc[mf8][1], A4, Bv[1][0], Bv[1][1]);
                mma8(o_acc[mf8][2], A4, Bv[2][0], Bv[2][1]);
            }
        }
    }

    __syncthreads();
    if (tid < 128) al_s[tid] = 1.f / l_s[tid];
    __syncthreads();
    #pragma unroll
    for (int mf8 = 0; mf8 < 8; mf8++) {
        float i0 = al_s[mf8*16 + a_];
        float i1 = al_s[mf8*16 + a_ + 8];
        #pragma unroll
        for (int nd = 0; nd < 3; nd++) {
            int d0 = db + nd*8 + 2*b_;
            long long r0 = (long long)d0*NP + n0 + mf8*16 + a_;
            Ob[r0]            = o_acc[mf8][nd][0] * i0;
            Ob[r0 + NP]       = o_acc[mf8][nd][1] * i0;
            Ob[r0 + 8]        = o_acc[mf8][nd][2] * i1;
            Ob[r0 + NP + 8]   = o_acc[mf8][nd][3] * i1;
        }
    }
}

// ---------------- kNN gather + VN-leaky + mean pool ----------------
__global__ __launch_bounds__(128) void gather_leaky(const float* __restrict__ G,
                                                    const int* __restrict__ knn,
                                                    float* __restrict__ X5)
{
    int bn = blockIdx.x;
    int b = bn >> 11, n = bn & 2047;
    int o = threadIdx.x;
    __shared__ int ridx[8];
    if (o < 8) ridx[o] = knn[((b*8 + o) << 11) + n];
    __syncthreads();
    const float* gc = G + (long long)bn*1536;
    float pc0 = gc[128 + o],        dc0 = gc[384 + o];
    float pc1 = gc[512 + 128 + o],  dc1 = gc[512 + 384 + o];
    float pc2 = gc[1024 + 128 + o], dc2 = gc[1024 + 384 + o];
    float a0 = 0.f, a1 = 0.f, a2 = 0.f;
    #pragma unroll
    for (int k = 0; k < 8; k++) {
        const float* gr = G + (long long)ridx[k]*1536;
        float p0 = gr[o] + pc0;
        float p1 = gr[512 + o] + pc1;
        float p2 = gr[1024 + o] + pc2;
        float d0 = gr[256 + o] + dc0;
        float d1 = gr[512 + 256 + o] + dc1;
        float d2 = gr[1024 + 256 + o] + dc2;
        float dot = p0*d0 + p1*d1 + p2*d2;
        if (dot < 0.f) {
            float f = 0.8f * dot / (d0*d0 + d1*d1 + d2*d2 + 1e-6f);
            p0 -= f*d0; p1 -= f*d1; p2 -= f*d2;
        }
        a0 += p0; a1 += p1; a2 += p2;
    }
    float* y = X5 + (long long)b*(2*NC*M3) + (long long)(128 + o)*M3 + n;
    y[0] = a0*0.125f; y[2048] = a1*0.125f; y[4096] = a2*0.125f;
}

// ---------------- elementwise VN-leaky ----------------
__global__ void leaky_ew(const float* __restrict__ P, const float* __restrict__ D,
                         float* __restrict__ Y)
{
    int idx = blockIdx.x*256 + threadIdx.x;
    int n = idx & 2047;
    int bo = idx >> 11;
    long long base = ((long long)bo*3 << 11) + n;
    float p0 = P[base], p1 = P[base + 2048], p2 = P[base + 4096];
    float d0 = D[base], d1 = D[base + 2048], d2 = D[base + 4096];
    float dot = p0*d0 + p1*d1 + p2*d2;
    if (dot < 0.f) {
        float f = 0.8f * dot / (d0*d0 + d1*d1 + d2*d2 + 1e-6f);
        p0 -= f*d0; p1 -= f*d1; p2 -= f*d2;
    }
    Y[base] = p0; Y[base + 2048] = p1; Y[base + 4096] = p2;
}

// ---------------- conv4 leaky + residual + output transpose ----------------
__global__ void final_k(const float* __restrict__ P, const float* __restrict__ D,
                        const float* __restrict__ vnx, float* __restrict__ out)
{
    int idx = blockIdx.x*256 + threadIdx.x;
    int n = idx & 2047;
    int o = (idx >> 11) & 127;
    int b = idx >> 18;
    long long base2 = (((long long)(b*NC + o))*3 << 11) + n;
    float p0 = P[base2], p1 = P[base2 + 2048], p2 = P[base2 + 4096];
    float d0 = D[base2], d1 = D[base2 + 2048], d2 = D[base2 + 4096];
    float dot = p0*d0 + p1*d1 + p2*d2;
    if (dot < 0.f) {
        float f = 0.8f * dot / (d0*d0 + d1*d1 + d2*d2 + 1e-6f);
        p0 -= f*d0; p1 -= f*d1; p2 -= f*d2;
    }
    float r0 = vnx[base2], r1 = vnx[base2 + 2048], r2 = vnx[base2 + 4096];
    float* q = out + ((long long)(b*NP + n))*ND + 3*o;
    q[0] = r0 + p0; q[1] = r1 + p1; q[2] = r2 + p2;
}

// ---------------- host ----------------
extern "C" void kernel_launch(void* const* d_in, const int* in_sizes, int n_in,
                              void* d_out, int out_size)
{
    (void)in_sizes; (void)n_in; (void)out_size;
    const float* x  = (const float*)d_in[0];
    const int* knn  = (const int*)d_in[1];
    const float* g1 = (const float*)d_in[2];
    const float* b1 = (const float*)d_in[3];
    const float* g2 = (const float*)d_in[4];
    const float* b2 = (const float*)d_in[5];
    const float* Wq = (const float*)d_in[6];
    const float* Wk = (const float*)d_in[7];
    const float* Wv = (const float*)d_in[8];
    const float* Wo = (const float*)d_in[9];
    const float* W1 = (const float*)d_in[10];
    const float* U1 = (const float*)d_in[11];
    const float* W2 = (const float*)d_in[12];
    const float* W3 = (const float*)d_in[13];
    const float* U3 = (const float*)d_in[14];
    const float* W4 = (const float*)d_in[15];
    const float* U4 = (const float*)d_in[16];
    float* out = (float*)d_out;

    float *normx,*q,*k,*v,*ao,*G,*x5,*vnx,*nx2,*p3,*d3,*h,*p4,*d4,*cw;
    cudaGetSymbolAddress((void**)&normx, g_normx);
    cudaGetSymbolAddress((void**)&q,  g_q);
    cudaGetSymbolAddress((void**)&k,  g_k);
    cudaGetSymbolAddress((void**)&v,  g_v);
    cudaGetSymbolAddress((void**)&ao, g_ao);
    cudaGetSymbolAddress((void**)&G,  g_G);
    cudaGetSymbolAddress((void**)&x5, g_x5);
    cudaGetSymbolAddress((void**)&vnx, g_vnx);
    cudaGetSymbolAddress((void**)&nx2, g_nx2);
    cudaGetSymbolAddress((void**)&p3, g_p3);
    cudaGetSymbolAddress((void**)&d3, g_d3);
    cudaGetSymbolAddress((void**)&h,  g_h);
    cudaGetSymbolAddress((void**)&p4, g_p4);
    cudaGetSymbolAddress((void**)&d4, g_d4);
    cudaGetSymbolAddress((void**)&cw, g_cw);

    cudaFuncSetAttribute(flash_tc, cudaFuncAttributeMaxDynamicSharedMemorySize, FTC_SMEM);

    prep_cw<<<256, 256>>>(W1, U1, cw);
    ln_k<<<NB*NP, 128>>>(x, g1, b1, normx, 0);

    long long sN = (long long)NC*M3;
    long long sQ = (long long)ND*M3;
    long long sX5 = (long long)2*NC*M3;

    gemm_k<<<dim3(48,3,NB), 256>>>(Wq, normx, q, nullptr, 128, M3, sN, 0, sQ, 0, M3, 1, 0, 0);
    gemm_k<<<dim3(48,3,NB), 256>>>(Wk, normx, k, nullptr, 128, M3, sN, 0, sQ, 0, M3, 1, 0, 0);
    gemm_k<<<dim3(48,3,NB), 256>>>(Wv, normx, v, nullptr, 128, M3, sN, 0, sQ, 0, M3, 1, 0, 0);

    flash_tc<<<dim3(16, NH, NB), 256, FTC_SMEM>>>(q, k, v, ao);

    gemm_k<<<dim3(48,1,NB), 256>>>(Wo, ao, x5, nullptr, 384, M3, sQ, 0, sX5, 0, M3, 1, 0, 0);

    gemm_k<<<dim3(16,4,12), 256>>>(cw, normx, G, nullptr, 128, M3,
                                   sN, 2048, (long long)NP*1536, 512, 1, 1536, 1, 0);
    gather_leaky<<<NB*NP, 128>>>(G, knn, x5);

    gemm_k<<<dim3(48,1,NB), 256>>>(W2, x5, vnx, x, 256, M3, sX5, 0, sN, 0, M3, 1, 0, 1);

    ln_k<<<NB*NP, 128>>>(vnx, g2, b2, nx2, 1);

    gemm_k<<<dim3(48,2,NB), 256>>>(W3, nx2, p3, nullptr, 128, M3, sN, 0, sX5, 0, M3, 1, 0, 0);
    gemm_k<<<dim3(48,2,NB), 256>>>(U3, nx2, d3, nullptr, 128, M3, sN, 0, sX5, 0, M3, 1, 0, 0);
    leaky_ew<<<NB*2*NC*NP/256, 256>>>(p3, d3, h);

    gemm_k<<<dim3(48,1,NB), 256>>>(W4, h, p4, nullptr, 256, M3, sX5, 0, sN, 0, M3, 1, 0, 0);
    gemm_k<<<dim3(48,1,NB), 256>>>(U4, h, d4, nullptr, 256, M3, sX5, 0, sN, 0, M3, 1, 0, 0);

    final_k<<<NB*NC*NP/256, 256>>>(p4, d4, vnx, out);
}

// round 5
// speedup vs baseline: 3.9667x; 1.5211x over previous
#include <cuda_runtime.h>
#include <cuda_bf16.h>
#include <math.h>

#define NB 4
#define NP 2048
#define NC 128
#define ND 384
#define NH 6
#define FD 192
#define M3 (3*NP)   // 6144

// ---------------- scratch ----------------
__device__ float g_normx[NB*NC*3*NP];
__device__ float g_q [NB*ND*3*NP];
__device__ float g_k [NB*ND*3*NP];
__device__ float g_v [NB*ND*3*NP];
__device__ float g_ao[NB*ND*3*NP];
__device__ float g_G [NB*NP*1536];
__device__ float g_x5[NB*2*NC*3*NP];
__device__ float g_vnx[NB*NC*3*NP];
__device__ float g_nx2[NB*NC*3*NP];
__device__ float g_p3[NB*2*NC*3*NP];
__device__ float g_d3[NB*2*NC*3*NP];
__device__ float g_h [NB*2*NC*3*NP];
__device__ float g_p4[NB*NC*3*NP];
__device__ float g_d4[NB*NC*3*NP];
__device__ float g_cw[512*128];

__device__ __forceinline__ unsigned f2tf(float f) {
    unsigned u;
    asm("cvt.rna.tf32.f32 %0, %1;" : "=r"(u) : "f"(f));
    return u;
}
__device__ __forceinline__ float f2tff(float f) {
    return __uint_as_float(f2tf(f));
}
__device__ __forceinline__ void mma8(float* d, const unsigned* a, unsigned b0, unsigned b1) {
    asm volatile("mma.sync.aligned.m16n8k8.row.col.f32.tf32.tf32.f32 "
                 "{%0,%1,%2,%3},{%4,%5,%6,%7},{%8,%9},{%0,%1,%2,%3};"
                 : "+f"(d[0]), "+f"(d[1]), "+f"(d[2]), "+f"(d[3])
                 : "r"(a[0]), "r"(a[1]), "r"(a[2]), "r"(a[3]), "r"(b0), "r"(b1));
}

// ---------------- weight prep ----------------
__global__ void prep_cw(const float* __restrict__ W1, const float* __restrict__ U1,
                        float* __restrict__ CW)
{
    int idx = blockIdx.x * 256 + threadIdx.x;
    if (idx >= 512*128) return;
    int col = idx >> 7;
    int c   = idx & 127;
    int a = col / 128;
    int o = col % 128;
    float v;
    if      (a == 0) v = W1[o*256 + c];
    else if (a == 1) v = W1[o*256 + 128 + c] - W1[o*256 + c];
    else if (a == 2) v = U1[o*256 + c];
    else             v = U1[o*256 + 128 + c] - U1[o*256 + c];
    CW[col*128 + c] = v;
}

// ---------------- vector-norm layernorm ----------------
__global__ __launch_bounds__(128) void ln_k(const float* __restrict__ in,
                                            const float* __restrict__ g,
                                            const float* __restrict__ bb,
                                            float* __restrict__ out, int mode)
{
    int bn = blockIdx.x;
    int b = bn >> 11, n = bn & 2047;
    int c = threadIdx.x;
    float v0, v1, v2;
    if (mode == 0) {
        const float* p = in + (long long)bn*384 + 3*c;
        v0 = p[0]; v1 = p[1]; v2 = p[2];
    } else {
        const float* p = in + ((long long)b*NC + c)*M3 + n;
        v0 = p[0]; v1 = p[2048]; v2 = p[4096];
    }
    float nrm = sqrtf(v0*v0 + v1*v1 + v2*v2 + 1e-6f);
    float s = nrm, s2 = nrm*nrm;
    for (int m = 16; m; m >>= 1) {
        s  += __shfl_xor_sync(0xffffffffu, s,  m);
        s2 += __shfl_xor_sync(0xffffffffu, s2, m);
    }
    __shared__ float sb[8];
    int w = c >> 5, lane = c & 31;
    if (!lane) { sb[w] = s; sb[4 + w] = s2; }
    __syncthreads();
    float ts  = sb[0] + sb[1] + sb[2] + sb[3];
    float ts2 = sb[4] + sb[5] + sb[6] + sb[7];
    float mu  = ts * (1.f/128.f);
    float var = ts2 * (1.f/128.f) - mu*mu;
    float nhat = (nrm - mu) / sqrtf(var + 1e-5f);
    float scale = (g[c]*nhat + bb[c]) / nrm;
    float* q = out + ((long long)b*NC + c)*M3 + n;
    q[0] = v0*scale; q[2048] = v1*scale; q[4096] = v2*scale;
}

// ---------------- tf32 tensor-core batched GEMM, double-buffered ----------------
__global__ __launch_bounds__(256, 2) void gemm_k(
    const float* __restrict__ W, const float* __restrict__ X, float* __restrict__ Y,
    const float* __restrict__ Res,
    int Cin, int ldx,
    long long xsb, long long xsi, long long ysb, long long ysi,
    int oso, int osm, int zflag, int mode)
{
    __shared__ float sw[2][16*136];
    __shared__ float sx[2][16*136];
    int z = blockIdx.z;
    int b  = zflag ? z/3 : z;
    int i3 = zflag ? z%3 : 0;
    const float* xb = X + (long long)b*xsb + (long long)i3*xsi;
    float* yb = Y + (long long)b*ysb + (long long)i3*ysi;
    int m0 = blockIdx.x * 128;
    int o0 = blockIdx.y * 128;
    int tid = threadIdx.x;
    int wid = tid >> 5, lane = tid & 31;
    int a_ = lane >> 2, b_ = lane & 3;
    int wy = wid >> 1, wx = wid & 1;

    int wrow = tid >> 2, wkc = (tid & 3) << 2;
    int xkr = tid >> 5, xmc = (tid & 31) << 2;
    const float* wp0 = W + (long long)(o0 + wrow)*Cin + wkc;
    const float* wp1 = W + (long long)(o0 + 64 + wrow)*Cin + wkc;
    const float* xp0 = xb + (long long)xkr*ldx + m0 + xmc;
    const float* xp1 = xb + (long long)(xkr + 8)*ldx + m0 + xmc;

    float4 pw0 = *(const float4*)(wp0);
    float4 pw1 = *(const float4*)(wp1);
    float4 px0 = *(const float4*)(xp0);
    float4 px1 = *(const float4*)(xp1);

    float acc[2][8][4];
    #pragma unroll
    for (int i = 0; i < 2; i++)
        #pragma unroll
        for (int j = 0; j < 8; j++)
            #pragma unroll
            for (int c = 0; c < 4; c++) acc[i][j][c] = 0.f;

    int nchunk = Cin >> 4;
    for (int ch = 0; ch < nchunk; ch++) {
        int buf = ch & 1;
        float* swb = sw[buf];
        float* sxb = sx[buf];
        swb[(wkc+0)*136 + wrow] = f2tff(pw0.x);
        swb[(wkc+1)*136 + wrow] = f2tff(pw0.y);
        swb[(wkc+2)*136 + wrow] = f2tff(pw0.z);
        swb[(wkc+3)*136 + wrow] = f2tff(pw0.w);
        swb[(wkc+0)*136 + wrow + 64] = f2tff(pw1.x);
        swb[(wkc+1)*136 + wrow + 64] = f2tff(pw1.y);
        swb[(wkc+2)*136 + wrow + 64] = f2tff(pw1.z);
        swb[(wkc+3)*136 + wrow + 64] = f2tff(pw1.w);
        float4 t0 = make_float4(f2tff(px0.x), f2tff(px0.y), f2tff(px0.z), f2tff(px0.w));
        float4 t1 = make_float4(f2tff(px1.x), f2tff(px1.y), f2tff(px1.z), f2tff(px1.w));
        *(float4*)(sxb + xkr*136 + xmc) = t0;
        *(float4*)(sxb + (xkr + 8)*136 + xmc) = t1;
        __syncthreads();
        if (ch + 1 < nchunk) {
            int k0 = (ch + 1) << 4;
            pw0 = *(const float4*)(wp0 + k0);
            pw1 = *(const float4*)(wp1 + k0);
            px0 = *(const float4*)(xp0 + (long long)k0*ldx);
            px1 = *(const float4*)(xp1 + (long long)k0*ldx);
        }
        #pragma unroll
        for (int kf = 0; kf < 2; kf++) {
            const float* wp = swb + (kf*8 + b_)*136 + wy*32 + a_;
            unsigned A[2][4];
            A[0][0] = __float_as_uint(wp[0]);   A[0][1] = __float_as_uint(wp[8]);
            A[0][2] = __float_as_uint(wp[544]); A[0][3] = __float_as_uint(wp[552]);
            A[1][0] = __float_as_uint(wp[16]);  A[1][1] = __float_as_uint(wp[24]);
            A[1][2] = __float_as_uint(wp[560]); A[1][3] = __float_as_uint(wp[568]);
            const float* xp = sxb + (kf*8 + b_)*136 + wx*64 + a_;
            #pragma unroll
            for (int nf = 0; nf < 8; nf++) {
                unsigned B0 = __float_as_uint(xp[nf*8]);
                unsigned B1 = __float_as_uint(xp[nf*8 + 544]);
                mma8(acc[0][nf], A[0], B0, B1);
                mma8(acc[1][nf], A[1], B0, B1);
            }
        }
    }

    int ob = o0 + wy*32, mb = m0 + wx*64;
    if (osm == 1) {
        #pragma unroll
        for (int mf = 0; mf < 2; mf++)
            #pragma unroll
            for (int nf = 0; nf < 8; nf++) {
                int o = ob + mf*16 + a_;
                int m = mb + nf*8 + 2*b_;
                float2 v0 = make_float2(acc[mf][nf][0], acc[mf][nf][1]);
                float2 v1 = make_float2(acc[mf][nf][2], acc[mf][nf][3]);
                if (mode == 1) {
                    long long rb = (long long)b*NP*ND;
                    v0.x += Res[rb + (long long)(m & 2047)*ND + 3*o + (m >> 11)];
                    v0.y += Res[rb + (long long)((m+1) & 2047)*ND + 3*o + ((m+1) >> 11)];
                    v1.x += Res[rb + (long long)(m & 2047)*ND + 3*(o+8) + (m >> 11)];
                    v1.y += Res[rb + (long long)((m+1) & 2047)*ND + 3*(o+8) + ((m+1) >> 11)];
                }
                *(float2*)(yb + (long long)o*oso + m) = v0;
                *(float2*)(yb + (long long)(o+8)*oso + m) = v1;
            }
    } else {
        #pragma unroll
        for (int mf = 0; mf < 2; mf++)
            #pragma unroll
            for (int nf = 0; nf < 8; nf++)
                #pragma unroll
                for (int c = 0; c < 4; c++) {
                    int o = ob + mf*16 + a_ + ((c >> 1) ? 8 : 0);
                    int m = mb + nf*8 + 2*b_ + (c & 1);
                    yb[(long long)o*oso + (long long)m*osm] = acc[mf][nf][c];
                }
    }
}

// ---------------- tf32 flash attention v3: 128q tile, 64-key stream, shared KV buffer ----------------
// Qs[192][136], KVs[192][72], Ps[64][136], state
#define FTC_SMEM ((192*136 + 192*72 + 64*136 + 896)*4)

__global__ __launch_bounds__(256) void flash_tc(const float* __restrict__ Q,
                                                const float* __restrict__ K,
                                                const float* __restrict__ V,
                                                float* __restrict__ O)
{
    extern __shared__ float sm[];
    float* Qs  = sm;                    // [192][136]
    float* KVs = Qs + 192*136;          // [192][72]
    float* Ps  = KVs + 192*72;          // [64 keys][136 rows]
    float* m_s  = Ps + 64*136;          // [128]
    float* l_s  = m_s + 128;            // [128]
    float* al_s = l_s + 128;            // [128]
    float* red  = al_s + 128;           // [256]
    float* red2 = red + 256;            // [256]

    int n0 = blockIdx.x * 128;
    long long hb = (long long)(blockIdx.z*NH + blockIdx.y) * FD * NP;
    const float* Qb = Q + hb;
    const float* Kb = K + hb;
    const float* Vb = V + hb;
    float* Ob = O + hb;

    int tid = threadIdx.x;
    int wid = tid >> 5, lane = tid & 31;
    int a_ = lane >> 2, b_ = lane & 3;
    int qg = wid >> 1, kh = wid & 1;    // QK: 32q x 32k per warp
    int db = wid * 24;                  // PV: 24-dim slice per warp

    for (int idx = tid; idx < 192*32; idx += 256) {
        int d = idx >> 5, c = (idx & 31) << 2;
        float4 v = *(const float4*)(Qb + (long long)d*NP + n0 + c);
        v.x = f2tff(v.x*0.125f); v.y = f2tff(v.y*0.125f);
        v.z = f2tff(v.z*0.125f); v.w = f2tff(v.w*0.125f);
        *(float4*)(Qs + d*136 + c) = v;
    }
    if (tid < 128) { m_s[tid] = -1e30f; l_s[tid] = 0.f; }

    float o_acc[8][3][4];
    #pragma unroll
    for (int i = 0; i < 8; i++)
        #pragma unroll
        for (int j = 0; j < 3; j++)
            #pragma unroll
            for (int c = 0; c < 4; c++) o_acc[i][j][c] = 0.f;

    for (int kt = 0; kt < NP; kt += 64) {
        __syncthreads();    // prev PV done; KVs free
        for (int idx = tid; idx < 192*16; idx += 256) {
            int d = idx >> 4, c = (idx & 15) << 2;
            float4 v = *(const float4*)(Kb + (long long)d*NP + kt + c);
            v.x = f2tff(v.x); v.y = f2tff(v.y);
            v.z = f2tff(v.z); v.w = f2tff(v.w);
            *(float4*)(KVs + d*72 + c) = v;
        }
        __syncthreads();

        // ---- QK: 32q x 32k per warp ----
        float s[2][4][4];
        #pragma unroll
        for (int mf = 0; mf < 2; mf++)
            #pragma unroll
            for (int nf = 0; nf < 4; nf++)
                #pragma unroll
                for (int c = 0; c < 4; c++) s[mf][nf][c] = 0.f;
        #pragma unroll
        for (int kf = 0; kf < 24; kf++) {
            const float* qp = Qs + (kf*8 + b_)*136 + qg*32 + a_;
            unsigned A[2][4];
            A[0][0] = __float_as_uint(qp[0]);   A[0][1] = __float_as_uint(qp[8]);
            A[0][2] = __float_as_uint(qp[544]); A[0][3] = __float_as_uint(qp[552]);
            A[1][0] = __float_as_uint(qp[16]);  A[1][1] = __float_as_uint(qp[24]);
            A[1][2] = __float_as_uint(qp[560]); A[1][3] = __float_as_uint(qp[568]);
            const float* kp = KVs + (kf*8 + b_)*72 + kh*32 + a_;
            #pragma unroll
            for (int nf = 0; nf < 4; nf++) {
                unsigned B0 = __float_as_uint(kp[nf*8]);
                unsigned B1 = __float_as_uint(kp[nf*8 + 288]);
                mma8(s[0][nf], A[0], B0, B1);
                mma8(s[1][nf], A[1], B0, B1);
            }
        }

        // ---- row max ----
        #pragma unroll
        for (int r = 0; r < 4; r++) {
            int mf = r >> 1, hi = (r & 1) << 1;
            float m = fmaxf(fmaxf(s[mf][0][hi], s[mf][0][hi+1]),
                            fmaxf(s[mf][1][hi], s[mf][1][hi+1]));
            m = fmaxf(m, fmaxf(fmaxf(s[mf][2][hi], s[mf][2][hi+1]),
                               fmaxf(s[mf][3][hi], s[mf][3][hi+1])));
            m = fmaxf(m, __shfl_xor_sync(0xffffffffu, m, 1));
            m = fmaxf(m, __shfl_xor_sync(0xffffffffu, m, 2));
            if (b_ == 0)
                red[(qg*32 + mf*16 + a_ + (r & 1)*8)*2 + kh] = m;
        }
        __syncthreads();
        if (tid < 128) {
            float tm = fmaxf(red[tid*2], red[tid*2 + 1]);
            float mn = fmaxf(m_s[tid], tm);
            al_s[tid] = __expf(m_s[tid] - mn);
            m_s[tid] = mn;
        }
        __syncthreads();

        // ---- exp + Ps + psum; rescale o_acc ----
        float psum[4] = {0.f, 0.f, 0.f, 0.f};
        #pragma unroll
        for (int mf = 0; mf < 2; mf++)
            #pragma unroll
            for (int c2 = 0; c2 < 2; c2++) {
                int row = qg*32 + mf*16 + a_ + c2*8;
                float mrow = m_s[row];
                #pragma unroll
                for (int nf = 0; nf < 4; nf++)
                    #pragma unroll
                    for (int c1 = 0; c1 < 2; c1++) {
                        float p = __expf(s[mf][nf][c2*2 + c1] - mrow);
                        psum[mf*2 + c2] += p;
                        Ps[(kh*32 + nf*8 + 2*b_ + c1)*136 + row] = p;
                    }
            }
        #pragma unroll
        for (int r = 0; r < 4; r++) {
            float ps = psum[r];
            ps += __shfl_xor_sync(0xffffffffu, ps, 1);
            ps += __shfl_xor_sync(0xffffffffu, ps, 2);
            if (b_ == 0)
                red2[(qg*32 + (r >> 1)*16 + a_ + (r & 1)*8)*2 + kh] = ps;
        }
        #pragma unroll
        for (int mf8 = 0; mf8 < 8; mf8++) {
            float al0 = al_s[mf8*16 + a_];
            float al1 = al_s[mf8*16 + a_ + 8];
            #pragma unroll
            for (int nd = 0; nd < 3; nd++) {
                o_acc[mf8][nd][0] *= al0; o_acc[mf8][nd][1] *= al0;
                o_acc[mf8][nd][2] *= al1; o_acc[mf8][nd][3] *= al1;
            }
        }
        __syncthreads();    // Ps + red2 visible; K fully consumed
        if (tid < 128)
            l_s[tid] = l_s[tid]*al_s[tid] + red2[tid*2] + red2[tid*2 + 1];
        // load V into the same KV buffer
        for (int idx = tid; idx < 192*16; idx += 256) {
            int d = idx >> 4, c = (idx & 15) << 2;
            float4 u = *(const float4*)(Vb + (long long)d*NP + kt + c);
            u.x = f2tff(u.x); u.y = f2tff(u.y);
            u.z = f2tff(u.z); u.w = f2tff(u.w);
            *(float4*)(KVs + d*72 + c) = u;
        }
        __syncthreads();

        // ---- PV: all 128 q x 24-dim slice per warp ----
        #pragma unroll
        for (int kf = 0; kf < 8; kf++) {
            unsigned Bv[3][2];
            #pragma unroll
            for (int nd = 0; nd < 3; nd++) {
                const float* vp = KVs + (db + nd*8 + a_)*72 + kf*8 + b_;
                Bv[nd][0] = __float_as_uint(vp[0]);
                Bv[nd][1] = __float_as_uint(vp[4]);
            }
            const float* pp = Ps + (kf*8 + b_)*136 + a_;
            #pragma unroll
            for (int mf8 = 0; mf8 < 8; mf8++) {
                unsigned A4[4];
                A4[0] = __float_as_uint(pp[mf8*16]);
                A4[1] = __float_as_uint(pp[mf8*16 + 8]);
                A4[2] = __float_as_uint(pp[mf8*16 + 544]);
                A4[3] = __float_as_uint(pp[mf8*16 + 552]);
                mma8(o_acc[mf8][0], A4, Bv[0][0], Bv[0][1]);
                mma8(o_acc[mf8][1], A4, Bv[1][0], Bv[1][1]);
                mma8(o_acc[mf8][2], A4, Bv[2][0], Bv[2][1]);
            }
        }
    }

    __syncthreads();
    if (tid < 128) al_s[tid] = 1.f / l_s[tid];
    __syncthreads();
    #pragma unroll
    for (int mf8 = 0; mf8 < 8; mf8++) {
        float i0 = al_s[mf8*16 + a_];
        float i1 = al_s[mf8*16 + a_ + 8];
        #pragma unroll
        for (int nd = 0; nd < 3; nd++) {
            int d0 = db + nd*8 + 2*b_;
            long long r0 = (long long)d0*NP + n0 + mf8*16 + a_;
            Ob[r0]            = o_acc[mf8][nd][0] * i0;
            Ob[r0 + NP]       = o_acc[mf8][nd][1] * i0;
            Ob[r0 + 8]        = o_acc[mf8][nd][2] * i1;
            Ob[r0 + NP + 8]   = o_acc[mf8][nd][3] * i1;
        }
    }
}

// ---------------- kNN gather + VN-leaky + mean pool ----------------
__global__ __launch_bounds__(128) void gather_leaky(const float* __restrict__ G,
                                                    const int* __restrict__ knn,
                                                    float* __restrict__ X5)
{
    int bn = blockIdx.x;
    int b = bn >> 11, n = bn & 2047;
    int o = threadIdx.x;
    __shared__ int ridx[8];
    if (o < 8) ridx[o] = knn[((b*8 + o) << 11) + n];
    __syncthreads();
    const float* gc = G + (long long)bn*1536;
    float pc0 = gc[128 + o],        dc0 = gc[384 + o];
    float pc1 = gc[512 + 128 + o],  dc1 = gc[512 + 384 + o];
    float pc2 = gc[1024 + 128 + o], dc2 = gc[1024 + 384 + o];
    float a0 = 0.f, a1 = 0.f, a2 = 0.f;
    #pragma unroll
    for (int k = 0; k < 8; k++) {
        const float* gr = G + (long long)ridx[k]*1536;
        float p0 = gr[o] + pc0;
        float p1 = gr[512 + o] + pc1;
        float p2 = gr[1024 + o] + pc2;
        float d0 = gr[256 + o] + dc0;
        float d1 = gr[512 + 256 + o] + dc1;
        float d2 = gr[1024 + 256 + o] + dc2;
        float dot = p0*d0 + p1*d1 + p2*d2;
        if (dot < 0.f) {
            float f = 0.8f * dot / (d0*d0 + d1*d1 + d2*d2 + 1e-6f);
            p0 -= f*d0; p1 -= f*d1; p2 -= f*d2;
        }
        a0 += p0; a1 += p1; a2 += p2;
    }
    float* y = X5 + (long long)b*(2*NC*M3) + (long long)(128 + o)*M3 + n;
    y[0] = a0*0.125f; y[2048] = a1*0.125f; y[4096] = a2*0.125f;
}

// ---------------- elementwise VN-leaky ----------------
__global__ void leaky_ew(const float* __restrict__ P, const float* __restrict__ D,
                         float* __restrict__ Y)
{
    int idx = blockIdx.x*256 + threadIdx.x;
    int n = idx & 2047;
    int bo = idx >> 11;
    long long base = ((long long)bo*3 << 11) + n;
    float p0 = P[base], p1 = P[base + 2048], p2 = P[base + 4096];
    float d0 = D[base], d1 = D[base + 2048], d2 = D[base + 4096];
    float dot = p0*d0 + p1*d1 + p2*d2;
    if (dot < 0.f) {
        float f = 0.8f * dot / (d0*d0 + d1*d1 + d2*d2 + 1e-6f);
        p0 -= f*d0; p1 -= f*d1; p2 -= f*d2;
    }
    Y[base] = p0; Y[base + 2048] = p1; Y[base + 4096] = p2;
}

// ---------------- conv4 leaky + residual + output transpose ----------------
__global__ void final_k(const float* __restrict__ P, const float* __restrict__ D,
                        const float* __restrict__ vnx, float* __restrict__ out)
{
    int idx = blockIdx.x*256 + threadIdx.x;
    int n = idx & 2047;
    int o = (idx >> 11) & 127;
    int b = idx >> 18;
    long long base2 = (((long long)(b*NC + o))*3 << 11) + n;
    float p0 = P[base2], p1 = P[base2 + 2048], p2 = P[base2 + 4096];
    float d0 = D[base2], d1 = D[base2 + 2048], d2 = D[base2 + 4096];
    float dot = p0*d0 + p1*d1 + p2*d2;
    if (dot < 0.f) {
        float f = 0.8f * dot / (d0*d0 + d1*d1 + d2*d2 + 1e-6f);
        p0 -= f*d0; p1 -= f*d1; p2 -= f*d2;
    }
    float r0 = vnx[base2], r1 = vnx[base2 + 2048], r2 = vnx[base2 + 4096];
    float* q = out + ((long long)(b*NP + n))*ND + 3*o;
    q[0] = r0 + p0; q[1] = r1 + p1; q[2] = r2 + p2;
}

// ---------------- host ----------------
extern "C" void kernel_launch(void* const* d_in, const int* in_sizes, int n_in,
                              void* d_out, int out_size)
{
    (void)in_sizes; (void)n_in; (void)out_size;
    const float* x  = (const float*)d_in[0];
    const int* knn  = (const int*)d_in[1];
    const float* g1 = (const float*)d_in[2];
    const float* b1 = (const float*)d_in[3];
    const float* g2 = (const float*)d_in[4];
    const float* b2 = (const float*)d_in[5];
    const float* Wq = (const float*)d_in[6];
    const float* Wk = (const float*)d_in[7];
    const float* Wv = (const float*)d_in[8];
    const float* Wo = (const float*)d_in[9];
    const float* W1 = (const float*)d_in[10];
    const float* U1 = (const float*)d_in[11];
    const float* W2 = (const float*)d_in[12];
    const float* W3 = (const float*)d_in[13];
    const float* U3 = (const float*)d_in[14];
    const float* W4 = (const float*)d_in[15];
    const float* U4 = (const float*)d_in[16];
    float* out = (float*)d_out;

    float *normx,*q,*k,*v,*ao,*G,*x5,*vnx,*nx2,*p3,*d3,*h,*p4,*d4,*cw;
    cudaGetSymbolAddress((void**)&normx, g_normx);
    cudaGetSymbolAddress((void**)&q,  g_q);
    cudaGetSymbolAddress((void**)&k,  g_k);
    cudaGetSymbolAddress((void**)&v,  g_v);
    cudaGetSymbolAddress((void**)&ao, g_ao);
    cudaGetSymbolAddress((void**)&G,  g_G);
    cudaGetSymbolAddress((void**)&x5, g_x5);
    cudaGetSymbolAddress((void**)&vnx, g_vnx);
    cudaGetSymbolAddress((void**)&nx2, g_nx2);
    cudaGetSymbolAddress((void**)&p3, g_p3);
    cudaGetSymbolAddress((void**)&d3, g_d3);
    cudaGetSymbolAddress((void**)&h,  g_h);
    cudaGetSymbolAddress((void**)&p4, g_p4);
    cudaGetSymbolAddress((void**)&d4, g_d4);
    cudaGetSymbolAddress((void**)&cw, g_cw);

    cudaFuncSetAttribute(flash_tc, cudaFuncAttributeMaxDynamicSharedMemorySize, FTC_SMEM);

    prep_cw<<<256, 256>>>(W1, U1, cw);
    ln_k<<<NB*NP, 128>>>(x, g1, b1, normx, 0);

    long long sN = (long long)NC*M3;
    long long sQ = (long long)ND*M3;
    long long sX5 = (long long)2*NC*M3;

    gemm_k<<<dim3(48,3,NB), 256>>>(Wq, normx, q, nullptr, 128, M3, sN, 0, sQ, 0, M3, 1, 0, 0);
    gemm_k<<<dim3(48,3,NB), 256>>>(Wk, normx, k, nullptr, 128, M3, sN, 0, sQ, 0, M3, 1, 0, 0);
    gemm_k<<<dim3(48,3,NB), 256>>>(Wv, normx, v, nullptr, 128, M3, sN, 0, sQ, 0, M3, 1, 0, 0);

    flash_tc<<<dim3(16, NH, NB), 256, FTC_SMEM>>>(q, k, v, ao);

    gemm_k<<<dim3(48,1,NB), 256>>>(Wo, ao, x5, nullptr, 384, M3, sQ, 0, sX5, 0, M3, 1, 0, 0);

    gemm_k<<<dim3(16,4,12), 256>>>(cw, normx, G, nullptr, 128, M3,
                                   sN, 2048, (long long)NP*1536, 512, 1, 1536, 1, 0);
    gather_leaky<<<NB*NP, 128>>>(G, knn, x5);

    gemm_k<<<dim3(48,1,NB), 256>>>(W2, x5, vnx, x, 256, M3, sX5, 0, sN, 0, M3, 1, 0, 1);

    ln_k<<<NB*NP, 128>>>(vnx, g2, b2, nx2, 1);

    gemm_k<<<dim3(48,2,NB), 256>>>(W3, nx2, p3, nullptr, 128, M3, sN, 0, sX5, 0, M3, 1, 0, 0);
    gemm_k<<<dim3(48,2,NB), 256>>>(U3, nx2, d3, nullptr, 128, M3, sN, 0, sX5, 0, M3, 1, 0, 0);
    leaky_ew<<<NB*2*NC*NP/256, 256>>>(p3, d3, h);

    gemm_k<<<dim3(48,1,NB), 256>>>(W4, h, p4, nullptr, 256, M3, sX5, 0, sN, 0, M3, 1, 0, 0);
    gemm_k<<<dim3(48,1,NB), 256>>>(U4, h, d4, nullptr, 256, M3, sX5, 0, sN, 0, M3, 1, 0, 0);

    final_k<<<NB*NC*NP/256, 256>>>(p4, d4, vnx, out);
}